// round 3
// baseline (speedup 1.0000x reference)
#include <cuda_runtime.h>
#include <math.h>

// ---------------------------------------------------------------------------
// AdaptiveLogSoftmax: per-token NLL.
//   head:  logits0 = (h@p0)@w0^T + b0  -> logsumexp over 20003, gather 1 col
//   tails: only for rows whose target falls in that cluster (compacted).
// No max pass needed: logit magnitudes are ~O(1), exp is safe in fp32.
// ---------------------------------------------------------------------------

#define NROWS 1024
#define HEAD_SIZE 20003
// cluster ends: [0,20000,40000,200000,267735]

// ---------------- scratch (static __device__, no allocations) --------------
__device__ float g_proj0[1024 * 1024];
__device__ float g_proj1[1024 * 256];
__device__ float g_proj2[1024 * 64];
__device__ float g_proj3[1024 * 16];
__device__ float g_S0[NROWS];      // head sum-exp
__device__ float g_St[NROWS];      // tail sum-exp (per row, its own cluster)
__device__ float g_ghead[NROWS];   // gathered head logit
__device__ float g_gtail[NROWS];   // gathered tail logit
__device__ int   g_rowlist[3 * NROWS];
__device__ int   g_count[3];
__device__ int   g_cluster[NROWS];

// ---------------- packed f32x2 FMA -----------------------------------------
#define FMA2(d, a, b) asm("fma.rn.f32x2 %0, %1, %2, %0;" : "+l"(d) : "l"(a), "l"(b))

__device__ __forceinline__ float2 upk(unsigned long long v) {
    float2 r;
    r.x = __uint_as_float((unsigned int)(v & 0xffffffffull));
    r.y = __uint_as_float((unsigned int)(v >> 32));
    return r;
}

// ---------------- tiled GEMM ------------------------------------------------
// MODE 0: C = A*B' (store / k-split atomic). MODE 1: sum-exp epilogue -> Ssum.
// BT=1: B is [Nc,K] row-major (NT, weights). BT=0: B is [K,Nc] row-major (NN).
// A is [M,K] row-major; rows optionally indirected via rowmap (tail clusters).
#define BM 128
#define BN 128
#define BK 8
#define ASTR 132
#define BSTR 258

template <int MODE, int BT>
__global__ void __launch_bounds__(256, 2) gemm_kernel(
    const float* __restrict__ A, const float* __restrict__ B,
    const float* __restrict__ bias, float* __restrict__ C,
    float* __restrict__ Ssum, int M, int Nc, int K,
    const int* __restrict__ rowmap, const int* __restrict__ countPtr)
{
    __shared__ __align__(16) float As[BK * ASTR];
    __shared__ __align__(16) float Bs[BK * BSTR];   // duplicated pairs: [k][2*col(+1)]

    int count = countPtr ? *countPtr : M;
    const int rowBase = blockIdx.y * BM;
    if (rowBase >= count) return;
    const int colBase = blockIdx.x * BN;

    const int tid = threadIdx.x;
    const int tx  = tid & 15;
    const int ty  = tid >> 4;

    // A loader: one float4 per thread per tile
    const int ar = tid >> 1;
    const int ak = (tid & 1) * 4;
    const int gA = rowBase + ar;
    const bool aval = (gA < count);
    const int arow = aval ? (rowmap ? rowmap[gA] : gA) : 0;
    const float* Aptr = A + (size_t)arow * K + ak;

    // B loader
    const int bc = tid >> 1;           // NT: col within tile
    const int bk = (tid & 1) * 4;      // NT: k offset
    const int nk = tid >> 5;           // NN: k row within tile
    const int nj = (tid & 31) * 4;     // NN: col offset
    bool bvalid;
    const float* Bbase;
    if (BT) {
        int g = colBase + bc;
        bvalid = (g < Nc);
        Bbase = B + (size_t)(bvalid ? g : 0) * K + bk;
    } else {
        int g = colBase + nj;
        bvalid = (g < Nc);
        Bbase = B + (size_t)nk * Nc + (bvalid ? g : 0);
    }

    const int ksplit = gridDim.z;
    const int Kchunk = K / ksplit;
    const int kbeg = blockIdx.z * Kchunk;
    const int kend = kbeg + Kchunk;

    float4 aReg, bReg;
    const float4 fz = make_float4(0.f, 0.f, 0.f, 0.f);
    aReg = aval ? *(const float4*)(Aptr + kbeg) : fz;
    if (BT) bReg = bvalid ? *(const float4*)(Bbase + kbeg) : fz;
    else    bReg = bvalid ? *(const float4*)(Bbase + (size_t)kbeg * Nc) : fz;

    unsigned long long acc[4][8];
#pragma unroll
    for (int i = 0; i < 4; i++)
#pragma unroll
        for (int j = 0; j < 8; j++) acc[i][j] = 0ull;

    for (int k0 = kbeg; k0 < kend; k0 += BK) {
        // stage to smem (A transposed; B duplicated pairwise)
        As[(ak + 0) * ASTR + ar] = aReg.x;
        As[(ak + 1) * ASTR + ar] = aReg.y;
        As[(ak + 2) * ASTR + ar] = aReg.z;
        As[(ak + 3) * ASTR + ar] = aReg.w;
        if (BT) {
            int c2 = 2 * bc;
            Bs[(bk + 0) * BSTR + c2] = bReg.x; Bs[(bk + 0) * BSTR + c2 + 1] = bReg.x;
            Bs[(bk + 1) * BSTR + c2] = bReg.y; Bs[(bk + 1) * BSTR + c2 + 1] = bReg.y;
            Bs[(bk + 2) * BSTR + c2] = bReg.z; Bs[(bk + 2) * BSTR + c2 + 1] = bReg.z;
            Bs[(bk + 3) * BSTR + c2] = bReg.w; Bs[(bk + 3) * BSTR + c2 + 1] = bReg.w;
        } else {
            float v[4] = {bReg.x, bReg.y, bReg.z, bReg.w};
#pragma unroll
            for (int q = 0; q < 4; q++) {
                int c2 = 2 * (nj + q);
                Bs[nk * BSTR + c2] = v[q];
                Bs[nk * BSTR + c2 + 1] = v[q];
            }
        }
        __syncthreads();

        const int kn = k0 + BK;
        if (kn < kend) {
            aReg = aval ? *(const float4*)(Aptr + kn) : fz;
            if (BT) bReg = bvalid ? *(const float4*)(Bbase + kn) : fz;
            else    bReg = bvalid ? *(const float4*)(Bbase + (size_t)kn * Nc) : fz;
        }

#pragma unroll
        for (int kk = 0; kk < BK; ++kk) {
            const unsigned long long* ap =
                reinterpret_cast<const unsigned long long*>(&As[kk * ASTR + ty * 8]);
            unsigned long long a0 = ap[0], a1 = ap[1], a2 = ap[2], a3 = ap[3];
            const unsigned long long* bp =
                reinterpret_cast<const unsigned long long*>(&Bs[kk * BSTR]);
            unsigned long long bb[8];
#pragma unroll
            for (int j = 0; j < 8; ++j) bb[j] = bp[tx + 16 * j];
#pragma unroll
            for (int j = 0; j < 8; ++j) {
                FMA2(acc[0][j], a0, bb[j]);
                FMA2(acc[1][j], a1, bb[j]);
                FMA2(acc[2][j], a2, bb[j]);
                FMA2(acc[3][j], a3, bb[j]);
            }
        }
        __syncthreads();
    }

    if (MODE == 0) {
#pragma unroll
        for (int j = 0; j < 8; ++j) {
            int gc = colBase + tx + 16 * j;
            if (gc < Nc) {
#pragma unroll
                for (int i2 = 0; i2 < 4; ++i2) {
                    float2 v = upk(acc[i2][j]);
                    int r = rowBase + ty * 8 + 2 * i2;
                    if (gridDim.z > 1) {
                        atomicAdd(&C[(size_t)r * Nc + gc], v.x);
                        atomicAdd(&C[(size_t)(r + 1) * Nc + gc], v.y);
                    } else {
                        C[(size_t)r * Nc + gc] = v.x;
                        C[(size_t)(r + 1) * Nc + gc] = v.y;
                    }
                }
            }
        }
    } else {
        float rs[8];
#pragma unroll
        for (int i = 0; i < 8; i++) rs[i] = 0.f;
#pragma unroll
        for (int j = 0; j < 8; ++j) {
            int gc = colBase + tx + 16 * j;
            if (gc < Nc) {
                float bv = bias[gc];
#pragma unroll
                for (int i2 = 0; i2 < 4; ++i2) {
                    float2 v = upk(acc[i2][j]);
                    rs[2 * i2]     += __expf(v.x + bv);
                    rs[2 * i2 + 1] += __expf(v.y + bv);
                }
            }
        }
#pragma unroll
        for (int i = 0; i < 8; ++i) {
            float v = rs[i];
            v += __shfl_down_sync(0xffffffffu, v, 8, 16);
            v += __shfl_down_sync(0xffffffffu, v, 4, 16);
            v += __shfl_down_sync(0xffffffffu, v, 2, 16);
            v += __shfl_down_sync(0xffffffffu, v, 1, 16);
            if (tx == 0) {
                int gr = rowBase + ty * 8 + i;
                if (gr < count) {
                    int n = rowmap ? rowmap[gr] : gr;
                    atomicAdd(&Ssum[n], v);
                }
            }
        }
    }
}

// ---------------- small kernels --------------------------------------------
__global__ void init_kernel() {
    int i = threadIdx.x;
    if (i < NROWS) { g_S0[i] = 0.f; g_St[i] = 0.f; }
    if (i < 3) g_count[i] = 0;
}

__global__ void classify_kernel(const int* __restrict__ target, int n) {
    int i = blockIdx.x * blockDim.x + threadIdx.x;
    if (i >= n) return;
    int t = target[i];
    int c = (t < 20000) ? 0 : (t < 40000) ? 1 : (t < 200000) ? 2 : 3;
    g_cluster[i] = c;
    if (c > 0) {
        int idx = atomicAdd(&g_count[c - 1], 1);
        g_rowlist[(c - 1) * NROWS + idx] = i;
    }
}

// one warp per row: head logit at target col (cluster 0) or cluster col
__global__ void gather_head_kernel(const float* __restrict__ w0,
                                   const float* __restrict__ b0,
                                   const int* __restrict__ target, int n) {
    int w = (blockIdx.x * blockDim.x + threadIdx.x) >> 5;
    int lane = threadIdx.x & 31;
    if (w >= n) return;
    int c = g_cluster[w];
    int col = (c == 0) ? target[w] : (HEAD_SIZE - c);
    const float4* pr = (const float4*)(g_proj0 + (size_t)w * 1024);
    const float4* wr = (const float4*)(w0 + (size_t)col * 1024);
    float s = 0.f;
    for (int i = lane; i < 256; i += 32) {
        float4 a = pr[i], b = wr[i];
        s += a.x * b.x + a.y * b.y + a.z * b.z + a.w * b.w;
    }
#pragma unroll
    for (int o = 16; o; o >>= 1) s += __shfl_down_sync(0xffffffffu, s, o);
    if (lane == 0) g_ghead[w] = s + b0[col];
}

// one warp per row (skip cluster 0): tail logit at (target - end)
__global__ void gather_tail_kernel(const float* __restrict__ w1, const float* __restrict__ b1,
                                   const float* __restrict__ w2, const float* __restrict__ b2,
                                   const float* __restrict__ w3, const float* __restrict__ b3,
                                   const int* __restrict__ target, int n) {
    int w = (blockIdx.x * blockDim.x + threadIdx.x) >> 5;
    int lane = threadIdx.x & 31;
    if (w >= n) return;
    int c = g_cluster[w];
    if (c == 0) return;
    const float* pr; const float* W; const float* bb; int K, off;
    if (c == 1)      { pr = g_proj1 + (size_t)w * 256; W = w1; bb = b1; K = 256; off = 20000; }
    else if (c == 2) { pr = g_proj2 + (size_t)w * 64;  W = w2; bb = b2; K = 64;  off = 40000; }
    else             { pr = g_proj3 + (size_t)w * 16;  W = w3; bb = b3; K = 16;  off = 200000; }
    int ti = target[w] - off;
    float s = 0.f;
    for (int k = lane; k < K; k += 32) s += pr[k] * W[(size_t)ti * K + k];
#pragma unroll
    for (int o = 16; o; o >>= 1) s += __shfl_down_sync(0xffffffffu, s, o);
    if (lane == 0) g_gtail[w] = s + bb[ti];
}

__global__ void combine_kernel(float* __restrict__ out, int n) {
    int i = blockIdx.x * blockDim.x + threadIdx.x;
    if (i >= n) return;
    float v = logf(g_S0[i]) - g_ghead[i];
    if (g_cluster[i] > 0) v += logf(g_St[i]) - g_gtail[i];
    out[i] = v;
}

// ---------------- launch ----------------------------------------------------
extern "C" void kernel_launch(void* const* d_in, const int* in_sizes, int n_in,
                              void* d_out, int out_size) {
    const float* hidden = (const float*)d_in[0];
    const int*   target = (const int*)d_in[1];
    const float* w0 = (const float*)d_in[2];
    const float* b0 = (const float*)d_in[3];
    const float* p0 = (const float*)d_in[4];
    const float* w1 = (const float*)d_in[5];
    const float* b1 = (const float*)d_in[6];
    const float* p1 = (const float*)d_in[7];
    const float* w2 = (const float*)d_in[8];
    const float* b2 = (const float*)d_in[9];
    const float* p2 = (const float*)d_in[10];
    const float* w3 = (const float*)d_in[11];
    const float* b3 = (const float*)d_in[12];
    const float* p3 = (const float*)d_in[13];
    float* out = (float*)d_out;

    float *proj0, *proj1, *proj2, *proj3, *S0, *St;
    int *rowlist, *cnt;
    cudaGetSymbolAddress((void**)&proj0, g_proj0);
    cudaGetSymbolAddress((void**)&proj1, g_proj1);
    cudaGetSymbolAddress((void**)&proj2, g_proj2);
    cudaGetSymbolAddress((void**)&proj3, g_proj3);
    cudaGetSymbolAddress((void**)&S0, g_S0);
    cudaGetSymbolAddress((void**)&St, g_St);
    cudaGetSymbolAddress((void**)&rowlist, g_rowlist);
    cudaGetSymbolAddress((void**)&cnt, g_count);

    const int N = NROWS;

    // zero proj buffers (k-split GEMMs accumulate atomically)
    cudaMemsetAsync(proj0, 0, sizeof(float) * 1024 * 1024, 0);
    cudaMemsetAsync(proj1, 0, sizeof(float) * 1024 * 256, 0);
    cudaMemsetAsync(proj2, 0, sizeof(float) * 1024 * 64, 0);
    cudaMemsetAsync(proj3, 0, sizeof(float) * 1024 * 16, 0);

    init_kernel<<<1, 1024>>>();
    classify_kernel<<<(N + 255) / 256, 256>>>(target, N);

    // projections: proj_i = hidden @ p_i   (NN, k-split for SM coverage)
    gemm_kernel<0, 0><<<dim3(8, 8, 2), 256>>>(hidden, p0, nullptr, proj0, nullptr, N, 1024, 1024, nullptr, nullptr);
    gemm_kernel<0, 0><<<dim3(2, 8, 4), 256>>>(hidden, p1, nullptr, proj1, nullptr, N, 256, 1024, nullptr, nullptr);
    gemm_kernel<0, 0><<<dim3(1, 8, 8), 256>>>(hidden, p2, nullptr, proj2, nullptr, N, 64, 1024, nullptr, nullptr);
    gemm_kernel<0, 0><<<dim3(1, 8, 8), 256>>>(hidden, p3, nullptr, proj3, nullptr, N, 16, 1024, nullptr, nullptr);

    // head: sum-exp over 20003 cols, all rows
    gemm_kernel<1, 1><<<dim3(157, 8, 1), 256>>>(proj0, w0, b0, nullptr, S0, N, HEAD_SIZE, 1024, nullptr, nullptr);

    // tails: sum-exp over each tail vocab, compacted rows only
    gemm_kernel<1, 1><<<dim3(157, 8, 1), 256>>>(proj1, w1, b1, nullptr, St, N, 20000, 256, rowlist + 0 * NROWS, cnt + 0);
    gemm_kernel<1, 1><<<dim3(1250, 8, 1), 256>>>(proj2, w2, b2, nullptr, St, N, 160000, 64, rowlist + 1 * NROWS, cnt + 1);
    gemm_kernel<1, 1><<<dim3(530, 8, 1), 256>>>(proj3, w3, b3, nullptr, St, N, 67735, 16, rowlist + 2 * NROWS, cnt + 2);

    // gathers + final combine
    gather_head_kernel<<<(N * 32 + 255) / 256, 256>>>(w0, b0, target, N);
    gather_tail_kernel<<<(N * 32 + 255) / 256, 256>>>(w1, b1, w2, b2, w3, b3, target, N);
    combine_kernel<<<(N + 255) / 256, 256>>>(out, N);
}

// round 4
// speedup vs baseline: 2.2573x; 2.2573x over previous
#include <cuda_runtime.h>
#include <math.h>
#include <stdint.h>

// ---------------------------------------------------------------------------
// AdaptiveLogSoftmax NLL, tensor-core (tf32 mma.sync) implementation.
//   head:  logits0 = (h@p0)@w0^T + b0  -> sum-exp over 20003 (no max pass
//          needed: logits are O(1)), gather 1 col
//   tails: only rows whose target falls in that cluster (device compaction).
// ---------------------------------------------------------------------------

#define NROWS 1024
#define HEAD_SIZE 20003

__device__ float g_proj0[1024 * 1024];
__device__ float g_proj1[1024 * 256];
__device__ float g_proj2[1024 * 64];
__device__ float g_proj3[1024 * 16];
__device__ float g_S0[NROWS];
__device__ float g_St[NROWS];
__device__ float g_ghead[NROWS];
__device__ float g_gtail[NROWS];
__device__ int   g_rowlist[3 * NROWS];
__device__ int   g_count[3];
__device__ int   g_cluster[NROWS];

__device__ __forceinline__ uint32_t f2tf(float f) {
    uint32_t r;
    asm("cvt.rna.tf32.f32 %0, %1;" : "=r"(r) : "f"(f));
    return r;
}

#define MMA_TF32(c, a, b)                                                     \
    asm volatile(                                                             \
        "mma.sync.aligned.m16n8k8.row.col.f32.tf32.tf32.f32 "                 \
        "{%0,%1,%2,%3},{%4,%5,%6,%7},{%8,%9},{%0,%1,%2,%3};"                  \
        : "+f"(c[0]), "+f"(c[1]), "+f"(c[2]), "+f"(c[3])                      \
        : "r"(a[0]), "r"(a[1]), "r"(a[2]), "r"(a[3]), "r"(b[0]), "r"(b[1]))

// ---------------------------------------------------------------------------
// Tiled tensor-core GEMM, 128x128x16 tile, 256 threads (8 warps: 2M x 4N,
// 64x32 per warp). MODE 0: C = A*B' stored (atomic if k-split). MODE 1:
// fused sum-exp(logit+bias) epilogue accumulated into Ssum.
// BT=1: B is [Nc,K] row-major (weights, NT). BT=0: B is [K,Nc] (proj, NN).
// A rows optionally indirected via rowmap + runtime count (tail compaction).
// ---------------------------------------------------------------------------
#define BM 128
#define BN 128
#define BKT 16
#define LDA 20   // padded row stride (floats); conflict-free for frag loads

template <int MODE, int BT>
__global__ void __launch_bounds__(256, 2) mma_gemm(
    const float* __restrict__ A, const float* __restrict__ B,
    const float* __restrict__ bias, float* __restrict__ C,
    float* __restrict__ Ssum, int M, int Nc, int K,
    const int* __restrict__ rowmap, const int* __restrict__ countPtr)
{
    __shared__ uint32_t As[BM * LDA];
    __shared__ uint32_t Bs[BN * LDA];
    __shared__ float rsum[BM];

    const int count = countPtr ? *countPtr : M;
    const int rowBase = blockIdx.y * BM;
    if (rowBase >= count) return;
    const int colBase = blockIdx.x * BN;

    const int tid  = threadIdx.x;
    const int lane = tid & 31;
    const int wid  = tid >> 5;
    const int mBase = (wid & 1) * 64;   // warp M offset
    const int nBase = (wid >> 1) * 32;  // warp N offset
    const int lq = lane >> 2;           // 0..7
    const int lr = lane & 3;            // 0..3

    if (MODE == 1 && tid < BM) rsum[tid] = 0.f;

    // ---- A loader: thread -> (row = tid/2, k-chunk of 8) ----
    const int ar  = tid >> 1;
    const int akk = (tid & 1) * 8;
    const int gA  = rowBase + ar;
    const bool aval = (gA < count);
    const int arow = aval ? (rowmap ? rowmap[gA] : gA) : 0;
    const float* Aptr = A + (size_t)arow * K + akk;

    // ---- B loader ----
    int br, bkk; bool bval; const float* Bptr;
    if (BT) {
        br  = tid >> 1;            // n within tile
        bkk = (tid & 1) * 8;       // k chunk
        bval = (colBase + br) < Nc;
        Bptr = B + (size_t)(bval ? colBase + br : 0) * K + bkk;
    } else {
        bkk = tid >> 4;            // k row (0..15)
        br  = (tid & 15) * 8;      // n start
        bval = (colBase + br) < Nc;   // Nc % 8 == 0 in all NN uses
        Bptr = B + colBase + br;
    }

    const int ksplit = gridDim.z;
    const int Kchunk = K / ksplit;
    const int kbeg = blockIdx.z * Kchunk;
    const int kend = kbeg + Kchunk;

    const float4 fz = make_float4(0.f, 0.f, 0.f, 0.f);
    float4 aR0, aR1, bR0, bR1;

    // prefetch first tile
    aR0 = aval ? *(const float4*)(Aptr + kbeg)     : fz;
    aR1 = aval ? *(const float4*)(Aptr + kbeg + 4) : fz;
    if (BT) {
        bR0 = bval ? *(const float4*)(Bptr + kbeg)     : fz;
        bR1 = bval ? *(const float4*)(Bptr + kbeg + 4) : fz;
    } else {
        bR0 = bval ? *(const float4*)(Bptr + (size_t)(kbeg + bkk) * Nc)     : fz;
        bR1 = bval ? *(const float4*)(Bptr + (size_t)(kbeg + bkk) * Nc + 4) : fz;
    }

    float acc[4][4][4];   // [mt][nt][reg]
#pragma unroll
    for (int i = 0; i < 4; i++)
#pragma unroll
        for (int j = 0; j < 4; j++)
#pragma unroll
            for (int r = 0; r < 4; r++) acc[i][j][r] = 0.f;

    for (int k0 = kbeg; k0 < kend; k0 += BKT) {
        // stage (fp32 -> tf32)
        {
            uint32_t* ap = &As[ar * LDA + akk];
            ap[0] = f2tf(aR0.x); ap[1] = f2tf(aR0.y); ap[2] = f2tf(aR0.z); ap[3] = f2tf(aR0.w);
            ap[4] = f2tf(aR1.x); ap[5] = f2tf(aR1.y); ap[6] = f2tf(aR1.z); ap[7] = f2tf(aR1.w);
            if (BT) {
                uint32_t* bp = &Bs[br * LDA + bkk];
                bp[0] = f2tf(bR0.x); bp[1] = f2tf(bR0.y); bp[2] = f2tf(bR0.z); bp[3] = f2tf(bR0.w);
                bp[4] = f2tf(bR1.x); bp[5] = f2tf(bR1.y); bp[6] = f2tf(bR1.z); bp[7] = f2tf(bR1.w);
            } else {
                float v[8] = {bR0.x, bR0.y, bR0.z, bR0.w, bR1.x, bR1.y, bR1.z, bR1.w};
#pragma unroll
                for (int q = 0; q < 8; q++) Bs[(br + q) * LDA + bkk] = f2tf(v[q]);
            }
        }
        __syncthreads();

        const int kn = k0 + BKT;
        if (kn < kend) {
            aR0 = aval ? *(const float4*)(Aptr + kn)     : fz;
            aR1 = aval ? *(const float4*)(Aptr + kn + 4) : fz;
            if (BT) {
                bR0 = bval ? *(const float4*)(Bptr + kn)     : fz;
                bR1 = bval ? *(const float4*)(Bptr + kn + 4) : fz;
            } else {
                bR0 = bval ? *(const float4*)(Bptr + (size_t)(kn + bkk) * Nc)     : fz;
                bR1 = bval ? *(const float4*)(Bptr + (size_t)(kn + bkk) * Nc + 4) : fz;
            }
        }

#pragma unroll
        for (int ks = 0; ks < BKT; ks += 8) {
            uint32_t af[4][4], bf[4][2];
#pragma unroll
            for (int mt = 0; mt < 4; mt++) {
                int r = mBase + mt * 16 + lq;
                int c = ks + lr;
                af[mt][0] = As[r * LDA + c];
                af[mt][1] = As[(r + 8) * LDA + c];
                af[mt][2] = As[r * LDA + c + 4];
                af[mt][3] = As[(r + 8) * LDA + c + 4];
            }
#pragma unroll
            for (int nt = 0; nt < 4; nt++) {
                int n = nBase + nt * 8 + lq;
                bf[nt][0] = Bs[n * LDA + ks + lr];
                bf[nt][1] = Bs[n * LDA + ks + 4 + lr];
            }
#pragma unroll
            for (int mt = 0; mt < 4; mt++)
#pragma unroll
                for (int nt = 0; nt < 4; nt++)
                    MMA_TF32(acc[mt][nt], af[mt], bf[nt]);
        }
        __syncthreads();
    }

    if (MODE == 0) {
#pragma unroll
        for (int mt = 0; mt < 4; mt++) {
            int r0 = rowBase + mBase + mt * 16 + lq;
#pragma unroll
            for (int nt = 0; nt < 4; nt++) {
                int gc = colBase + nBase + nt * 8 + 2 * lr;
                if (gc < Nc) {
                    float* p0 = C + (size_t)r0 * Nc + gc;
                    float* p1 = C + (size_t)(r0 + 8) * Nc + gc;
                    if (ksplit > 1) {
                        atomicAdd(p0,     acc[mt][nt][0]);
                        atomicAdd(p0 + 1, acc[mt][nt][1]);
                        atomicAdd(p1,     acc[mt][nt][2]);
                        atomicAdd(p1 + 1, acc[mt][nt][3]);
                    } else {
                        p0[0] = acc[mt][nt][0]; p0[1] = acc[mt][nt][1];
                        p1[0] = acc[mt][nt][2]; p1[1] = acc[mt][nt][3];
                    }
                }
            }
        }
    } else {
        float rs[4][2];
#pragma unroll
        for (int mt = 0; mt < 4; mt++) { rs[mt][0] = 0.f; rs[mt][1] = 0.f; }
#pragma unroll
        for (int nt = 0; nt < 4; nt++) {
            int gc = colBase + nBase + nt * 8 + 2 * lr;
            bool v0 = gc < Nc, v1 = (gc + 1) < Nc;
            float bv0 = v0 ? bias[gc] : 0.f;
            float bv1 = v1 ? bias[gc + 1] : 0.f;
#pragma unroll
            for (int mt = 0; mt < 4; mt++) {
                if (v0) {
                    rs[mt][0] += __expf(acc[mt][nt][0] + bv0);
                    rs[mt][1] += __expf(acc[mt][nt][2] + bv0);
                }
                if (v1) {
                    rs[mt][0] += __expf(acc[mt][nt][1] + bv1);
                    rs[mt][1] += __expf(acc[mt][nt][3] + bv1);
                }
            }
        }
#pragma unroll
        for (int mt = 0; mt < 4; mt++)
#pragma unroll
            for (int h = 0; h < 2; h++) {
                float v = rs[mt][h];
                v += __shfl_xor_sync(0xffffffffu, v, 1);
                v += __shfl_xor_sync(0xffffffffu, v, 2);
                if (lr == 0)
                    atomicAdd(&rsum[mBase + mt * 16 + h * 8 + lq], v);
            }
        __syncthreads();
        if (tid < BM) {
            int gr = rowBase + tid;
            if (gr < count) {
                int n = rowmap ? rowmap[gr] : gr;
                atomicAdd(&Ssum[n], rsum[tid]);
            }
        }
    }
}

// ---------------- small kernels --------------------------------------------
__global__ void init_kernel() {
    int i = threadIdx.x;
    if (i < NROWS) { g_S0[i] = 0.f; g_St[i] = 0.f; }
    if (i < 3) g_count[i] = 0;
}

__global__ void classify_kernel(const int* __restrict__ target, int n) {
    int i = blockIdx.x * blockDim.x + threadIdx.x;
    if (i >= n) return;
    int t = target[i];
    int c = (t < 20000) ? 0 : (t < 40000) ? 1 : (t < 200000) ? 2 : 3;
    g_cluster[i] = c;
    if (c > 0) {
        int idx = atomicAdd(&g_count[c - 1], 1);
        g_rowlist[(c - 1) * NROWS + idx] = i;
    }
}

__global__ void gather_head_kernel(const float* __restrict__ w0,
                                   const float* __restrict__ b0,
                                   const int* __restrict__ target, int n) {
    int w = (blockIdx.x * blockDim.x + threadIdx.x) >> 5;
    int lane = threadIdx.x & 31;
    if (w >= n) return;
    int c = g_cluster[w];
    int col = (c == 0) ? target[w] : (HEAD_SIZE - c);
    const float4* pr = (const float4*)(g_proj0 + (size_t)w * 1024);
    const float4* wr = (const float4*)(w0 + (size_t)col * 1024);
    float s = 0.f;
    for (int i = lane; i < 256; i += 32) {
        float4 a = pr[i], b = wr[i];
        s += a.x * b.x + a.y * b.y + a.z * b.z + a.w * b.w;
    }
#pragma unroll
    for (int o = 16; o; o >>= 1) s += __shfl_down_sync(0xffffffffu, s, o);
    if (lane == 0) g_ghead[w] = s + b0[col];
}

__global__ void gather_tail_kernel(const float* __restrict__ w1, const float* __restrict__ b1,
                                   const float* __restrict__ w2, const float* __restrict__ b2,
                                   const float* __restrict__ w3, const float* __restrict__ b3,
                                   const int* __restrict__ target, int n) {
    int w = (blockIdx.x * blockDim.x + threadIdx.x) >> 5;
    int lane = threadIdx.x & 31;
    if (w >= n) return;
    int c = g_cluster[w];
    if (c == 0) return;
    const float* pr; const float* W; const float* bb; int K, off;
    if (c == 1)      { pr = g_proj1 + (size_t)w * 256; W = w1; bb = b1; K = 256; off = 20000; }
    else if (c == 2) { pr = g_proj2 + (size_t)w * 64;  W = w2; bb = b2; K = 64;  off = 40000; }
    else             { pr = g_proj3 + (size_t)w * 16;  W = w3; bb = b3; K = 16;  off = 200000; }
    int ti = target[w] - off;
    float s = 0.f;
    for (int k = lane; k < K; k += 32) s += pr[k] * W[(size_t)ti * K + k];
#pragma unroll
    for (int o = 16; o; o >>= 1) s += __shfl_down_sync(0xffffffffu, s, o);
    if (lane == 0) g_gtail[w] = s + bb[ti];
}

__global__ void combine_kernel(float* __restrict__ out, int n) {
    int i = blockIdx.x * blockDim.x + threadIdx.x;
    if (i >= n) return;
    float v = logf(g_S0[i]) - g_ghead[i];
    if (g_cluster[i] > 0) v += logf(g_St[i]) - g_gtail[i];
    out[i] = v;
}

// ---------------- launch ----------------------------------------------------
extern "C" void kernel_launch(void* const* d_in, const int* in_sizes, int n_in,
                              void* d_out, int out_size) {
    const float* hidden = (const float*)d_in[0];
    const int*   target = (const int*)d_in[1];
    const float* w0 = (const float*)d_in[2];
    const float* b0 = (const float*)d_in[3];
    const float* p0 = (const float*)d_in[4];
    const float* w1 = (const float*)d_in[5];
    const float* b1 = (const float*)d_in[6];
    const float* p1 = (const float*)d_in[7];
    const float* w2 = (const float*)d_in[8];
    const float* b2 = (const float*)d_in[9];
    const float* p2 = (const float*)d_in[10];
    const float* w3 = (const float*)d_in[11];
    const float* b3 = (const float*)d_in[12];
    const float* p3 = (const float*)d_in[13];
    float* out = (float*)d_out;

    float *proj0, *proj1, *proj2, *proj3, *S0, *St;
    int *rowlist, *cnt;
    cudaGetSymbolAddress((void**)&proj0, g_proj0);
    cudaGetSymbolAddress((void**)&proj1, g_proj1);
    cudaGetSymbolAddress((void**)&proj2, g_proj2);
    cudaGetSymbolAddress((void**)&proj3, g_proj3);
    cudaGetSymbolAddress((void**)&S0, g_S0);
    cudaGetSymbolAddress((void**)&St, g_St);
    cudaGetSymbolAddress((void**)&rowlist, g_rowlist);
    cudaGetSymbolAddress((void**)&cnt, g_count);

    const int N = NROWS;

    // zero proj buffers (k-split GEMMs accumulate atomically)
    cudaMemsetAsync(proj0, 0, sizeof(float) * 1024 * 1024, 0);
    cudaMemsetAsync(proj1, 0, sizeof(float) * 1024 * 256, 0);
    cudaMemsetAsync(proj2, 0, sizeof(float) * 1024 * 64, 0);
    cudaMemsetAsync(proj3, 0, sizeof(float) * 1024 * 16, 0);

    init_kernel<<<1, 1024>>>();
    classify_kernel<<<(N + 255) / 256, 256>>>(target, N);

    // projections: proj_i = hidden @ p_i  (NN, k-split for SM coverage)
    mma_gemm<0, 0><<<dim3(8, 8, 2), 256>>>(hidden, p0, nullptr, proj0, nullptr, N, 1024, 1024, nullptr, nullptr);
    mma_gemm<0, 0><<<dim3(2, 8, 4), 256>>>(hidden, p1, nullptr, proj1, nullptr, N, 256, 1024, nullptr, nullptr);
    mma_gemm<0, 0><<<dim3(1, 8, 8), 256>>>(hidden, p2, nullptr, proj2, nullptr, N, 64, 1024, nullptr, nullptr);
    mma_gemm<0, 0><<<dim3(1, 8, 8), 256>>>(hidden, p3, nullptr, proj3, nullptr, N, 16, 1024, nullptr, nullptr);

    // head: sum-exp over 20003 cols, all rows
    mma_gemm<1, 1><<<dim3(157, 8, 1), 256>>>(proj0, w0, b0, nullptr, S0, N, HEAD_SIZE, 1024, nullptr, nullptr);

    // tails: sum-exp over each tail vocab, compacted rows only
    mma_gemm<1, 1><<<dim3(157, 8, 1), 256>>>(proj1, w1, b1, nullptr, St, N, 20000, 256, rowlist + 0 * NROWS, cnt + 0);
    mma_gemm<1, 1><<<dim3(1250, 8, 1), 256>>>(proj2, w2, b2, nullptr, St, N, 160000, 64, rowlist + 1 * NROWS, cnt + 1);
    mma_gemm<1, 1><<<dim3(530, 8, 1), 256>>>(proj3, w3, b3, nullptr, St, N, 67735, 16, rowlist + 2 * NROWS, cnt + 2);

    gather_head_kernel<<<(N * 32 + 255) / 256, 256>>>(w0, b0, target, N);
    gather_tail_kernel<<<(N * 32 + 255) / 256, 256>>>(w1, b1, w2, b2, w3, b3, target, N);
    combine_kernel<<<(N + 255) / 256, 256>>>(out, N);
}

// round 5
// speedup vs baseline: 2.6873x; 1.1905x over previous
#include <cuda_runtime.h>
#include <math.h>
#include <stdint.h>

// ---------------------------------------------------------------------------
// AdaptiveLogSoftmax NLL.
//   head:  logits0 = (h@p0)@w0^T + b0 -> sum-exp over 20003 (logits O(1),
//          no max pass needed), gather 1 col in fp32
//   tails: only rows whose target falls in that cluster (device compaction).
// Big GEMMs (head, tail1, tail2): bf16 m16n8k16 tensor cores, fp32 accum.
// Small GEMMs (proj*, tail3 K=16): tf32 m16n8k8 path.
// ---------------------------------------------------------------------------

#define NROWS 1024
#define HEAD_SIZE 20003

__device__ float g_proj0[1024 * 1024];
__device__ float g_proj1[1024 * 256];
__device__ float g_proj2[1024 * 64];
__device__ float g_proj3[1024 * 16];
__device__ float g_S0[NROWS];
__device__ float g_St[NROWS];
__device__ float g_ghead[NROWS];
__device__ float g_gtail[NROWS];
__device__ int   g_rowlist[3 * NROWS];
__device__ int   g_count[3];
__device__ int   g_cluster[NROWS];

__device__ __forceinline__ uint32_t f2tf(float f) {
    uint32_t r;
    asm("cvt.rna.tf32.f32 %0, %1;" : "=r"(r) : "f"(f));
    return r;
}
__device__ __forceinline__ uint32_t packbf(float lo, float hi) {
    uint32_t r;
    asm("cvt.rn.bf16x2.f32 %0, %1, %2;" : "=r"(r) : "f"(hi), "f"(lo));
    return r;
}

#define MMA_TF32(c, a, b)                                                     \
    asm volatile(                                                             \
        "mma.sync.aligned.m16n8k8.row.col.f32.tf32.tf32.f32 "                 \
        "{%0,%1,%2,%3},{%4,%5,%6,%7},{%8,%9},{%0,%1,%2,%3};"                  \
        : "+f"(c[0]), "+f"(c[1]), "+f"(c[2]), "+f"(c[3])                      \
        : "r"(a[0]), "r"(a[1]), "r"(a[2]), "r"(a[3]), "r"(b[0]), "r"(b[1]))

#define MMA_BF16(c, a, b)                                                     \
    asm volatile(                                                             \
        "mma.sync.aligned.m16n8k16.row.col.f32.bf16.bf16.f32 "                \
        "{%0,%1,%2,%3},{%4,%5,%6,%7},{%8,%9},{%0,%1,%2,%3};"                  \
        : "+f"(c[0]), "+f"(c[1]), "+f"(c[2]), "+f"(c[3])                      \
        : "r"(a[0]), "r"(a[1]), "r"(a[2]), "r"(a[3]), "r"(b[0]), "r"(b[1]))

#define LDA 20   // padded word stride: conflict-free for fragment LDS

// ===========================================================================
// bf16 GEMM + fused sum-exp epilogue. B is [Nc,K] row-major (NT weights).
// 128x128x32 tile, 256 threads (8 warps: 2Mx4N, 64x32 per warp).
// Requires K % 32 == 0. A rows indirected via rowmap + runtime count.
// ===========================================================================
__global__ void __launch_bounds__(256, 2) mma_sumexp_bf16(
    const float* __restrict__ A, const float* __restrict__ B,
    const float* __restrict__ bias, float* __restrict__ Ssum,
    int M, int Nc, int K,
    const int* __restrict__ rowmap, const int* __restrict__ countPtr)
{
    __shared__ uint32_t As[128 * LDA];   // bf16x2 words, 16 used per row
    __shared__ uint32_t Bs[128 * LDA];
    __shared__ float rsum[128];

    const int count = countPtr ? *countPtr : M;
    const int rowBase = blockIdx.y * 128;
    if (rowBase >= count) return;
    const int colBase = blockIdx.x * 128;

    const int tid  = threadIdx.x;
    const int lane = tid & 31;
    const int wid  = tid >> 5;
    const int mBase = (wid & 1) * 64;
    const int nBase = (wid >> 1) * 32;
    const int lq = lane >> 2;
    const int lr = lane & 3;

    if (tid < 128) rsum[tid] = 0.f;

    // A loader: row = tid/2, k-half of 16 floats
    const int ar  = tid >> 1;
    const int akk = (tid & 1) * 16;
    const int gA  = rowBase + ar;
    const bool aval = (gA < count);
    const int arow = aval ? (rowmap ? rowmap[gA] : gA) : 0;
    const float* Aptr = A + (size_t)arow * K + akk;

    // B loader: col = tid/2, k-half of 16 floats (always reads valid memory)
    const int br  = tid >> 1;
    const int bkk = (tid & 1) * 16;
    const int gB  = colBase + br;
    const float* Bptr = B + (size_t)(gB < Nc ? gB : 0) * K + bkk;

    uint32_t aW[8], bW[8];
#define CVLOAD(dst, ptr)                                                      \
    {                                                                         \
        const float4* _p = (const float4*)(ptr);                              \
        float4 v0 = _p[0], v1 = _p[1], v2 = _p[2], v3 = _p[3];                \
        dst[0] = packbf(v0.x, v0.y); dst[1] = packbf(v0.z, v0.w);             \
        dst[2] = packbf(v1.x, v1.y); dst[3] = packbf(v1.z, v1.w);             \
        dst[4] = packbf(v2.x, v2.y); dst[5] = packbf(v2.z, v2.w);             \
        dst[6] = packbf(v3.x, v3.y); dst[7] = packbf(v3.z, v3.w);             \
    }
    CVLOAD(aW, Aptr);
    CVLOAD(bW, Bptr);

    float acc[4][4][4];
#pragma unroll
    for (int i = 0; i < 4; i++)
#pragma unroll
        for (int j = 0; j < 4; j++)
#pragma unroll
            for (int r = 0; r < 4; r++) acc[i][j][r] = 0.f;

    for (int k0 = 0; k0 < K; k0 += 32) {
        {
            uint32_t* ap = &As[ar * LDA + (akk >> 1)];
            uint32_t* bp = &Bs[br * LDA + (bkk >> 1)];
#pragma unroll
            for (int j = 0; j < 8; j++) { ap[j] = aW[j]; bp[j] = bW[j]; }
        }
        __syncthreads();

        const int kn = k0 + 32;
        if (kn < K) {
            CVLOAD(aW, Aptr + kn);
            CVLOAD(bW, Bptr + kn);
        }

#pragma unroll
        for (int ks = 0; ks < 2; ++ks) {
            const int w0 = ks * 8;
            uint32_t af[4][4], bf[4][2];
#pragma unroll
            for (int mt = 0; mt < 4; mt++) {
                int r = mBase + mt * 16 + lq;
                af[mt][0] = As[r * LDA + w0 + lr];
                af[mt][1] = As[(r + 8) * LDA + w0 + lr];
                af[mt][2] = As[r * LDA + w0 + 4 + lr];
                af[mt][3] = As[(r + 8) * LDA + w0 + 4 + lr];
            }
#pragma unroll
            for (int nt = 0; nt < 4; nt++) {
                int n = nBase + nt * 8 + lq;
                bf[nt][0] = Bs[n * LDA + w0 + lr];
                bf[nt][1] = Bs[n * LDA + w0 + 4 + lr];
            }
#pragma unroll
            for (int mt = 0; mt < 4; mt++)
#pragma unroll
                for (int nt = 0; nt < 4; nt++)
                    MMA_BF16(acc[mt][nt], af[mt], bf[nt]);
        }
        __syncthreads();
    }

    // fused sum-exp epilogue
    float rs[4][2];
#pragma unroll
    for (int mt = 0; mt < 4; mt++) { rs[mt][0] = 0.f; rs[mt][1] = 0.f; }
#pragma unroll
    for (int nt = 0; nt < 4; nt++) {
        int gc = colBase + nBase + nt * 8 + 2 * lr;
        bool v0 = gc < Nc, v1 = (gc + 1) < Nc;
        float bv0 = v0 ? bias[gc] : 0.f;
        float bv1 = v1 ? bias[gc + 1] : 0.f;
#pragma unroll
        for (int mt = 0; mt < 4; mt++) {
            if (v0) {
                rs[mt][0] += __expf(acc[mt][nt][0] + bv0);
                rs[mt][1] += __expf(acc[mt][nt][2] + bv0);
            }
            if (v1) {
                rs[mt][0] += __expf(acc[mt][nt][1] + bv1);
                rs[mt][1] += __expf(acc[mt][nt][3] + bv1);
            }
        }
    }
#pragma unroll
    for (int mt = 0; mt < 4; mt++)
#pragma unroll
        for (int h = 0; h < 2; h++) {
            float v = rs[mt][h];
            v += __shfl_xor_sync(0xffffffffu, v, 1);
            v += __shfl_xor_sync(0xffffffffu, v, 2);
            if (lr == 0)
                atomicAdd(&rsum[mBase + mt * 16 + h * 8 + lq], v);
        }
    __syncthreads();
    if (tid < 128) {
        int gr = rowBase + tid;
        if (gr < count) {
            int n = rowmap ? rowmap[gr] : gr;
            atomicAdd(&Ssum[n], rsum[tid]);
        }
    }
}

// ===========================================================================
// tf32 GEMM (proj NN store path + tail3 K=16 sum-exp). 128x128x16 tile.
// ===========================================================================
template <int MODE, int BT>
__global__ void __launch_bounds__(256, 2) mma_gemm(
    const float* __restrict__ A, const float* __restrict__ B,
    const float* __restrict__ bias, float* __restrict__ C,
    float* __restrict__ Ssum, int M, int Nc, int K,
    const int* __restrict__ rowmap, const int* __restrict__ countPtr)
{
    __shared__ uint32_t As[128 * LDA];
    __shared__ uint32_t Bs[128 * LDA];
    __shared__ float rsum[128];

    const int count = countPtr ? *countPtr : M;
    const int rowBase = blockIdx.y * 128;
    if (rowBase >= count) return;
    const int colBase = blockIdx.x * 128;

    const int tid  = threadIdx.x;
    const int lane = tid & 31;
    const int wid  = tid >> 5;
    const int mBase = (wid & 1) * 64;
    const int nBase = (wid >> 1) * 32;
    const int lq = lane >> 2;
    const int lr = lane & 3;

    if (MODE == 1 && tid < 128) rsum[tid] = 0.f;

    const int ar  = tid >> 1;
    const int akk = (tid & 1) * 8;
    const int gA  = rowBase + ar;
    const bool aval = (gA < count);
    const int arow = aval ? (rowmap ? rowmap[gA] : gA) : 0;
    const float* Aptr = A + (size_t)arow * K + akk;

    int br, bkk; bool bval; const float* Bptr;
    if (BT) {
        br  = tid >> 1;
        bkk = (tid & 1) * 8;
        bval = (colBase + br) < Nc;
        Bptr = B + (size_t)(bval ? colBase + br : 0) * K + bkk;
    } else {
        bkk = tid >> 4;
        br  = (tid & 15) * 8;
        bval = (colBase + br) < Nc;
        Bptr = B + colBase + br;
    }

    const int ksplit = gridDim.z;
    const int Kchunk = K / ksplit;
    const int kbeg = blockIdx.z * Kchunk;
    const int kend = kbeg + Kchunk;

    const float4 fz = make_float4(0.f, 0.f, 0.f, 0.f);
    float4 aR0, aR1, bR0, bR1;
    aR0 = aval ? *(const float4*)(Aptr + kbeg)     : fz;
    aR1 = aval ? *(const float4*)(Aptr + kbeg + 4) : fz;
    if (BT) {
        bR0 = bval ? *(const float4*)(Bptr + kbeg)     : fz;
        bR1 = bval ? *(const float4*)(Bptr + kbeg + 4) : fz;
    } else {
        bR0 = bval ? *(const float4*)(Bptr + (size_t)(kbeg + bkk) * Nc)     : fz;
        bR1 = bval ? *(const float4*)(Bptr + (size_t)(kbeg + bkk) * Nc + 4) : fz;
    }

    float acc[4][4][4];
#pragma unroll
    for (int i = 0; i < 4; i++)
#pragma unroll
        for (int j = 0; j < 4; j++)
#pragma unroll
            for (int r = 0; r < 4; r++) acc[i][j][r] = 0.f;

    for (int k0 = kbeg; k0 < kend; k0 += 16) {
        {
            uint32_t* ap = &As[ar * LDA + akk];
            ap[0] = f2tf(aR0.x); ap[1] = f2tf(aR0.y); ap[2] = f2tf(aR0.z); ap[3] = f2tf(aR0.w);
            ap[4] = f2tf(aR1.x); ap[5] = f2tf(aR1.y); ap[6] = f2tf(aR1.z); ap[7] = f2tf(aR1.w);
            if (BT) {
                uint32_t* bp = &Bs[br * LDA + bkk];
                bp[0] = f2tf(bR0.x); bp[1] = f2tf(bR0.y); bp[2] = f2tf(bR0.z); bp[3] = f2tf(bR0.w);
                bp[4] = f2tf(bR1.x); bp[5] = f2tf(bR1.y); bp[6] = f2tf(bR1.z); bp[7] = f2tf(bR1.w);
            } else {
                float v[8] = {bR0.x, bR0.y, bR0.z, bR0.w, bR1.x, bR1.y, bR1.z, bR1.w};
#pragma unroll
                for (int q = 0; q < 8; q++) Bs[(br + q) * LDA + bkk] = f2tf(v[q]);
            }
        }
        __syncthreads();

        const int kn = k0 + 16;
        if (kn < kend) {
            aR0 = aval ? *(const float4*)(Aptr + kn)     : fz;
            aR1 = aval ? *(const float4*)(Aptr + kn + 4) : fz;
            if (BT) {
                bR0 = bval ? *(const float4*)(Bptr + kn)     : fz;
                bR1 = bval ? *(const float4*)(Bptr + kn + 4) : fz;
            } else {
                bR0 = bval ? *(const float4*)(Bptr + (size_t)(kn + bkk) * Nc)     : fz;
                bR1 = bval ? *(const float4*)(Bptr + (size_t)(kn + bkk) * Nc + 4) : fz;
            }
        }

#pragma unroll
        for (int ks = 0; ks < 16; ks += 8) {
            uint32_t af[4][4], bf[4][2];
#pragma unroll
            for (int mt = 0; mt < 4; mt++) {
                int r = mBase + mt * 16 + lq;
                int c = ks + lr;
                af[mt][0] = As[r * LDA + c];
                af[mt][1] = As[(r + 8) * LDA + c];
                af[mt][2] = As[r * LDA + c + 4];
                af[mt][3] = As[(r + 8) * LDA + c + 4];
            }
#pragma unroll
            for (int nt = 0; nt < 4; nt++) {
                int n = nBase + nt * 8 + lq;
                bf[nt][0] = Bs[n * LDA + ks + lr];
                bf[nt][1] = Bs[n * LDA + ks + 4 + lr];
            }
#pragma unroll
            for (int mt = 0; mt < 4; mt++)
#pragma unroll
                for (int nt = 0; nt < 4; nt++)
                    MMA_TF32(acc[mt][nt], af[mt], bf[nt]);
        }
        __syncthreads();
    }

    if (MODE == 0) {
#pragma unroll
        for (int mt = 0; mt < 4; mt++) {
            int r0 = rowBase + mBase + mt * 16 + lq;
#pragma unroll
            for (int nt = 0; nt < 4; nt++) {
                int gc = colBase + nBase + nt * 8 + 2 * lr;
                if (gc < Nc) {
                    float* p0 = C + (size_t)r0 * Nc + gc;
                    float* p1 = C + (size_t)(r0 + 8) * Nc + gc;
                    if (ksplit > 1) {
                        atomicAdd(p0,     acc[mt][nt][0]);
                        atomicAdd(p0 + 1, acc[mt][nt][1]);
                        atomicAdd(p1,     acc[mt][nt][2]);
                        atomicAdd(p1 + 1, acc[mt][nt][3]);
                    } else {
                        p0[0] = acc[mt][nt][0]; p0[1] = acc[mt][nt][1];
                        p1[0] = acc[mt][nt][2]; p1[1] = acc[mt][nt][3];
                    }
                }
            }
        }
    } else {
        float rs[4][2];
#pragma unroll
        for (int mt = 0; mt < 4; mt++) { rs[mt][0] = 0.f; rs[mt][1] = 0.f; }
#pragma unroll
        for (int nt = 0; nt < 4; nt++) {
            int gc = colBase + nBase + nt * 8 + 2 * lr;
            bool v0 = gc < Nc, v1 = (gc + 1) < Nc;
            float bv0 = v0 ? bias[gc] : 0.f;
            float bv1 = v1 ? bias[gc + 1] : 0.f;
#pragma unroll
            for (int mt = 0; mt < 4; mt++) {
                if (v0) {
                    rs[mt][0] += __expf(acc[mt][nt][0] + bv0);
                    rs[mt][1] += __expf(acc[mt][nt][2] + bv0);
                }
                if (v1) {
                    rs[mt][0] += __expf(acc[mt][nt][1] + bv1);
                    rs[mt][1] += __expf(acc[mt][nt][3] + bv1);
                }
            }
        }
#pragma unroll
        for (int mt = 0; mt < 4; mt++)
#pragma unroll
            for (int h = 0; h < 2; h++) {
                float v = rs[mt][h];
                v += __shfl_xor_sync(0xffffffffu, v, 1);
                v += __shfl_xor_sync(0xffffffffu, v, 2);
                if (lr == 0)
                    atomicAdd(&rsum[mBase + mt * 16 + h * 8 + lq], v);
            }
        __syncthreads();
        if (tid < 128) {
            int gr = rowBase + tid;
            if (gr < count) {
                int n = rowmap ? rowmap[gr] : gr;
                atomicAdd(&Ssum[n], rsum[tid]);
            }
        }
    }
}

// ---------------- small kernels --------------------------------------------
__global__ void init_kernel() {
    int i = threadIdx.x;
    if (i < NROWS) { g_S0[i] = 0.f; g_St[i] = 0.f; }
    if (i < 3) g_count[i] = 0;
}

__global__ void classify_kernel(const int* __restrict__ target, int n) {
    int i = blockIdx.x * blockDim.x + threadIdx.x;
    if (i >= n) return;
    int t = target[i];
    int c = (t < 20000) ? 0 : (t < 40000) ? 1 : (t < 200000) ? 2 : 3;
    g_cluster[i] = c;
    if (c > 0) {
        int idx = atomicAdd(&g_count[c - 1], 1);
        g_rowlist[(c - 1) * NROWS + idx] = i;
    }
}

__global__ void gather_head_kernel(const float* __restrict__ w0,
                                   const float* __restrict__ b0,
                                   const int* __restrict__ target, int n) {
    int w = (blockIdx.x * blockDim.x + threadIdx.x) >> 5;
    int lane = threadIdx.x & 31;
    if (w >= n) return;
    int c = g_cluster[w];
    int col = (c == 0) ? target[w] : (HEAD_SIZE - c);
    const float4* pr = (const float4*)(g_proj0 + (size_t)w * 1024);
    const float4* wr = (const float4*)(w0 + (size_t)col * 1024);
    float s = 0.f;
    for (int i = lane; i < 256; i += 32) {
        float4 a = pr[i], b = wr[i];
        s += a.x * b.x + a.y * b.y + a.z * b.z + a.w * b.w;
    }
#pragma unroll
    for (int o = 16; o; o >>= 1) s += __shfl_down_sync(0xffffffffu, s, o);
    if (lane == 0) g_ghead[w] = s + b0[col];
}

__global__ void gather_tail_kernel(const float* __restrict__ w1, const float* __restrict__ b1,
                                   const float* __restrict__ w2, const float* __restrict__ b2,
                                   const float* __restrict__ w3, const float* __restrict__ b3,
                                   const int* __restrict__ target, int n) {
    int w = (blockIdx.x * blockDim.x + threadIdx.x) >> 5;
    int lane = threadIdx.x & 31;
    if (w >= n) return;
    int c = g_cluster[w];
    if (c == 0) return;
    const float* pr; const float* W; const float* bb; int K, off;
    if (c == 1)      { pr = g_proj1 + (size_t)w * 256; W = w1; bb = b1; K = 256; off = 20000; }
    else if (c == 2) { pr = g_proj2 + (size_t)w * 64;  W = w2; bb = b2; K = 64;  off = 40000; }
    else             { pr = g_proj3 + (size_t)w * 16;  W = w3; bb = b3; K = 16;  off = 200000; }
    int ti = target[w] - off;
    float s = 0.f;
    for (int k = lane; k < K; k += 32) s += pr[k] * W[(size_t)ti * K + k];
#pragma unroll
    for (int o = 16; o; o >>= 1) s += __shfl_down_sync(0xffffffffu, s, o);
    if (lane == 0) g_gtail[w] = s + bb[ti];
}

__global__ void combine_kernel(float* __restrict__ out, int n) {
    int i = blockIdx.x * blockDim.x + threadIdx.x;
    if (i >= n) return;
    float v = logf(g_S0[i]) - g_ghead[i];
    if (g_cluster[i] > 0) v += logf(g_St[i]) - g_gtail[i];
    out[i] = v;
}

// ---------------- launch ----------------------------------------------------
extern "C" void kernel_launch(void* const* d_in, const int* in_sizes, int n_in,
                              void* d_out, int out_size) {
    const float* hidden = (const float*)d_in[0];
    const int*   target = (const int*)d_in[1];
    const float* w0 = (const float*)d_in[2];
    const float* b0 = (const float*)d_in[3];
    const float* p0 = (const float*)d_in[4];
    const float* w1 = (const float*)d_in[5];
    const float* b1 = (const float*)d_in[6];
    const float* p1 = (const float*)d_in[7];
    const float* w2 = (const float*)d_in[8];
    const float* b2 = (const float*)d_in[9];
    const float* p2 = (const float*)d_in[10];
    const float* w3 = (const float*)d_in[11];
    const float* b3 = (const float*)d_in[12];
    const float* p3 = (const float*)d_in[13];
    float* out = (float*)d_out;

    float *proj0, *proj1, *proj2, *proj3, *S0, *St;
    int *rowlist, *cnt;
    cudaGetSymbolAddress((void**)&proj0, g_proj0);
    cudaGetSymbolAddress((void**)&proj1, g_proj1);
    cudaGetSymbolAddress((void**)&proj2, g_proj2);
    cudaGetSymbolAddress((void**)&proj3, g_proj3);
    cudaGetSymbolAddress((void**)&S0, g_S0);
    cudaGetSymbolAddress((void**)&St, g_St);
    cudaGetSymbolAddress((void**)&rowlist, g_rowlist);
    cudaGetSymbolAddress((void**)&cnt, g_count);

    const int N = NROWS;

    cudaMemsetAsync(proj0, 0, sizeof(float) * 1024 * 1024, 0);
    cudaMemsetAsync(proj1, 0, sizeof(float) * 1024 * 256, 0);
    cudaMemsetAsync(proj2, 0, sizeof(float) * 1024 * 64, 0);
    cudaMemsetAsync(proj3, 0, sizeof(float) * 1024 * 16, 0);

    init_kernel<<<1, 1024>>>();
    classify_kernel<<<(N + 255) / 256, 256>>>(target, N);

    // projections: proj_i = hidden @ p_i  (tf32 NN, k-split for SM coverage)
    mma_gemm<0, 0><<<dim3(8, 8, 2), 256>>>(hidden, p0, nullptr, proj0, nullptr, N, 1024, 1024, nullptr, nullptr);
    mma_gemm<0, 0><<<dim3(2, 8, 4), 256>>>(hidden, p1, nullptr, proj1, nullptr, N, 256, 1024, nullptr, nullptr);
    mma_gemm<0, 0><<<dim3(1, 8, 8), 256>>>(hidden, p2, nullptr, proj2, nullptr, N, 64, 1024, nullptr, nullptr);
    mma_gemm<0, 0><<<dim3(1, 8, 8), 256>>>(hidden, p3, nullptr, proj3, nullptr, N, 16, 1024, nullptr, nullptr);

    // head: bf16 sum-exp over 20003 cols, all rows
    mma_sumexp_bf16<<<dim3(157, 8, 1), 256>>>(proj0, w0, b0, S0, N, HEAD_SIZE, 1024, nullptr, nullptr);

    // tails: sum-exp over each tail vocab, compacted rows only
    mma_sumexp_bf16<<<dim3(157, 8, 1), 256>>>(proj1, w1, b1, St, N, 20000, 256, rowlist + 0 * NROWS, cnt + 0);
    mma_sumexp_bf16<<<dim3(1250, 8, 1), 256>>>(proj2, w2, b2, St, N, 160000, 64, rowlist + 1 * NROWS, cnt + 1);
    mma_gemm<1, 1><<<dim3(530, 8, 1), 256>>>(proj3, w3, b3, nullptr, St, N, 67735, 16, rowlist + 2 * NROWS, cnt + 2);

    gather_head_kernel<<<(N * 32 + 255) / 256, 256>>>(w0, b0, target, N);
    gather_tail_kernel<<<(N * 32 + 255) / 256, 256>>>(w1, b1, w2, b2, w3, b3, target, N);
    combine_kernel<<<(N + 255) / 256, 256>>>(out, N);
}

// round 6
// speedup vs baseline: 3.6898x; 1.3731x over previous
#include <cuda_runtime.h>
#include <cuda_bf16.h>
#include <math.h>
#include <stdint.h>

// ---------------------------------------------------------------------------
// AdaptiveLogSoftmax NLL.
//   prep:   concat proj weights -> wcat; convert w0/w1/w2 -> bf16
//   proj:   proj_cat = hidden @ wcat (tf32), stored fp32 + bf16
//   head:   sum-exp over 20003 logits (bf16 mma + ldmatrix, fused epilogue)
//   tails:  sum-exp per cluster, row-compacted
//   gather: exact fp32 dot for the target logit
// ---------------------------------------------------------------------------

#define NROWS 1024
#define HEAD_SIZE 20003
#define PCW 1360   // concat width: 1024 + 256 + 64 + 16

__device__ __align__(16) float          g_wcat[1024 * PCW];      // weights concat
__device__ __align__(16) float          g_proj[NROWS * PCW];     // fp32 projections
__device__ __align__(16) __nv_bfloat16  g_projb[NROWS * PCW];    // bf16 projections
__device__ __align__(16) __nv_bfloat16  g_w0b[20003 * 1024];
__device__ __align__(16) __nv_bfloat16  g_w1b[20000 * 256];
__device__ __align__(16) __nv_bfloat16  g_w2b[160000 * 64];
__device__ float g_S0[NROWS];
__device__ float g_St[NROWS];
__device__ float g_ghead[NROWS];
__device__ float g_gtail[NROWS];
__device__ int   g_rowlist[3 * NROWS];
__device__ int   g_count[3];
__device__ int   g_cluster[NROWS];

__device__ __forceinline__ uint32_t f2tf(float f) {
    uint32_t r;
    asm("cvt.rna.tf32.f32 %0, %1;" : "=r"(r) : "f"(f));
    return r;
}
__device__ __forceinline__ uint32_t packbf(float lo, float hi) {
    uint32_t r;
    asm("cvt.rn.bf16x2.f32 %0, %1, %2;" : "=r"(r) : "f"(hi), "f"(lo));
    return r;
}

#define MMA_TF32(c, a, b)                                                     \
    asm volatile(                                                             \
        "mma.sync.aligned.m16n8k8.row.col.f32.tf32.tf32.f32 "                 \
        "{%0,%1,%2,%3},{%4,%5,%6,%7},{%8,%9},{%0,%1,%2,%3};"                  \
        : "+f"(c[0]), "+f"(c[1]), "+f"(c[2]), "+f"(c[3])                      \
        : "r"(a[0]), "r"(a[1]), "r"(a[2]), "r"(a[3]), "r"(b[0]), "r"(b[1]))

#define MMA_BF16(c, a0, a1, a2, a3, b0, b1)                                   \
    asm volatile(                                                             \
        "mma.sync.aligned.m16n8k16.row.col.f32.bf16.bf16.f32 "                \
        "{%0,%1,%2,%3},{%4,%5,%6,%7},{%8,%9},{%0,%1,%2,%3};"                  \
        : "+f"(c[0]), "+f"(c[1]), "+f"(c[2]), "+f"(c[3])                      \
        : "r"(a0), "r"(a1), "r"(a2), "r"(a3), "r"(b0), "r"(b1))

#define LDSM4(r0, r1, r2, r3, addr)                                           \
    asm volatile("ldmatrix.sync.aligned.m8n8.x4.shared.b16 {%0,%1,%2,%3}, [%4];" \
        : "=r"(r0), "=r"(r1), "=r"(r2), "=r"(r3) : "r"(addr))

#define LDW 20   // smem word stride per row: 16 data + 4 pad (conflict-free)

// ===========================================================================
// bf16 GEMM + fused sum-exp.  A: [.,lda] bf16 row-major (rowmap-indirected).
// B: [Nc,K] bf16 row-major.  128x128x32 tile, 256 thr, 8 warps (2Mx4N).
// ===========================================================================
__global__ void __launch_bounds__(256, 2) bf16_sumexp(
    const __nv_bfloat16* __restrict__ A, int lda,
    const __nv_bfloat16* __restrict__ B,
    const float* __restrict__ bias, float* __restrict__ Ssum,
    int M, int Nc, int K,
    const int* __restrict__ rowmap, const int* __restrict__ countPtr)
{
    __shared__ __align__(16) uint32_t As[128 * LDW];
    __shared__ __align__(16) uint32_t Bs[128 * LDW];
    __shared__ float rsum[128];

    const int count = countPtr ? *countPtr : M;
    const int rowBase = blockIdx.y * 128;
    if (rowBase >= count) return;
    const int colBase = blockIdx.x * 128;

    const int tid  = threadIdx.x;
    const int lane = tid & 31;
    const int wid  = tid >> 5;
    const int mBase = (wid & 1) * 64;
    const int nBase = (wid >> 1) * 32;
    const int lq = lane >> 2;
    const int lr = lane & 3;

    if (tid < 128) rsum[tid] = 0.f;

    // loaders: row = tid/2, half = 16 bf16 (32B = 2 uint4)
    const int ar   = tid >> 1;
    const int half = tid & 1;
    const int gA   = rowBase + ar;
    const bool aval = (gA < count);
    const int arow = aval ? (rowmap ? rowmap[gA] : gA) : 0;
    const char* Ag = (const char*)(A + (size_t)arow * lda + half * 16);
    const int gB = colBase + ar;
    const char* Bg = (const char*)(B + (size_t)(gB < Nc ? gB : 0) * K + half * 16);

    uint4 aV0, aV1, bV0, bV1;
    aV0 = ((const uint4*)Ag)[0]; aV1 = ((const uint4*)Ag)[1];
    bV0 = ((const uint4*)Bg)[0]; bV1 = ((const uint4*)Bg)[1];

    const uint32_t asb = (uint32_t)__cvta_generic_to_shared(As);
    const uint32_t bsb = (uint32_t)__cvta_generic_to_shared(Bs);
    const uint32_t aBase = asb + ((mBase + (lane & 15)) * LDW + (lane >> 4) * 4) * 4;
    const uint32_t bBase = bsb + ((nBase + lane) * LDW) * 4;

    float acc[4][4][4];
#pragma unroll
    for (int i = 0; i < 4; i++)
#pragma unroll
        for (int j = 0; j < 4; j++)
#pragma unroll
            for (int r = 0; r < 4; r++) acc[i][j][r] = 0.f;

    for (int k0 = 0; k0 < K; k0 += 32) {
        {
            uint4* ap = (uint4*)&As[ar * LDW + half * 8];
            uint4* bp = (uint4*)&Bs[ar * LDW + half * 8];
            ap[0] = aV0; ap[1] = aV1;
            bp[0] = bV0; bp[1] = bV1;
        }
        __syncthreads();

        const int kn = k0 + 32;
        if (kn < K) {
            aV0 = ((const uint4*)(Ag + kn * 2))[0];
            aV1 = ((const uint4*)(Ag + kn * 2))[1];
            bV0 = ((const uint4*)(Bg + kn * 2))[0];
            bV1 = ((const uint4*)(Bg + kn * 2))[1];
        }

#pragma unroll
        for (int c = 0; c < 2; ++c) {
            uint32_t af[4][4], b0r[4], b1r[4];
            LDSM4(b0r[0], b0r[1], b0r[2], b0r[3], bBase + c * 32);
            LDSM4(b1r[0], b1r[1], b1r[2], b1r[3], bBase + c * 32 + 16);
#pragma unroll
            for (int mt = 0; mt < 4; mt++)
                LDSM4(af[mt][0], af[mt][1], af[mt][2], af[mt][3],
                      aBase + mt * (16 * LDW * 4) + c * 32);
#pragma unroll
            for (int mt = 0; mt < 4; mt++)
#pragma unroll
                for (int nt = 0; nt < 4; nt++)
                    MMA_BF16(acc[mt][nt],
                             af[mt][0], af[mt][1], af[mt][2], af[mt][3],
                             b0r[nt], b1r[nt]);
        }
        __syncthreads();
    }

    // fused sum-exp epilogue
    float rs[4][2];
#pragma unroll
    for (int mt = 0; mt < 4; mt++) { rs[mt][0] = 0.f; rs[mt][1] = 0.f; }
#pragma unroll
    for (int nt = 0; nt < 4; nt++) {
        int gc = colBase + nBase + nt * 8 + 2 * lr;
        bool v0 = gc < Nc, v1 = (gc + 1) < Nc;
        float bv0 = v0 ? bias[gc] : 0.f;
        float bv1 = v1 ? bias[gc + 1] : 0.f;
#pragma unroll
        for (int mt = 0; mt < 4; mt++) {
            if (v0) {
                rs[mt][0] += __expf(acc[mt][nt][0] + bv0);
                rs[mt][1] += __expf(acc[mt][nt][2] + bv0);
            }
            if (v1) {
                rs[mt][0] += __expf(acc[mt][nt][1] + bv1);
                rs[mt][1] += __expf(acc[mt][nt][3] + bv1);
            }
        }
    }
#pragma unroll
    for (int mt = 0; mt < 4; mt++)
#pragma unroll
        for (int h = 0; h < 2; h++) {
            float v = rs[mt][h];
            v += __shfl_xor_sync(0xffffffffu, v, 1);
            v += __shfl_xor_sync(0xffffffffu, v, 2);
            if (lr == 0)
                atomicAdd(&rsum[mBase + mt * 16 + h * 8 + lq], v);
        }
    __syncthreads();
    if (tid < 128) {
        int gr = rowBase + tid;
        if (gr < count) {
            int n = rowmap ? rowmap[gr] : gr;
            atomicAdd(&Ssum[n], rsum[tid]);
        }
    }
}

// ===========================================================================
// tf32 GEMM. MODE 0: store C fp32 (+ optional bf16 copy). MODE 1: sum-exp.
// BT=1: B [Nc,K] row-major; BT=0: B [K,Nc] row-major. A lda parameterized.
// ===========================================================================
template <int MODE, int BT>
__global__ void __launch_bounds__(256, 2) mma_gemm(
    const float* __restrict__ A, int lda, const float* __restrict__ B,
    const float* __restrict__ bias, float* __restrict__ C,
    __nv_bfloat16* __restrict__ Cb,
    float* __restrict__ Ssum, int M, int Nc, int K,
    const int* __restrict__ rowmap, const int* __restrict__ countPtr)
{
    __shared__ uint32_t As[128 * LDW];
    __shared__ uint32_t Bs[128 * LDW];
    __shared__ float rsum[128];

    const int count = countPtr ? *countPtr : M;
    const int rowBase = blockIdx.y * 128;
    if (rowBase >= count) return;
    const int colBase = blockIdx.x * 128;

    const int tid  = threadIdx.x;
    const int lane = tid & 31;
    const int wid  = tid >> 5;
    const int mBase = (wid & 1) * 64;
    const int nBase = (wid >> 1) * 32;
    const int lq = lane >> 2;
    const int lr = lane & 3;

    if (MODE == 1 && tid < 128) rsum[tid] = 0.f;

    const int ar  = tid >> 1;
    const int akk = (tid & 1) * 8;
    const int gA  = rowBase + ar;
    const bool aval = (gA < count);
    const int arow = aval ? (rowmap ? rowmap[gA] : gA) : 0;
    const float* Aptr = A + (size_t)arow * lda + akk;

    int br, bkk; bool bval; const float* Bptr;
    if (BT) {
        br  = tid >> 1;
        bkk = (tid & 1) * 8;
        bval = (colBase + br) < Nc;
        Bptr = B + (size_t)(bval ? colBase + br : 0) * K + bkk;
    } else {
        bkk = tid >> 4;
        br  = (tid & 15) * 8;
        bval = (colBase + br) < Nc;
        Bptr = B + colBase + (bval ? br : 0);
    }

    const float4 fz = make_float4(0.f, 0.f, 0.f, 0.f);
    float4 aR0, aR1, bR0, bR1;
    aR0 = aval ? *(const float4*)(Aptr)     : fz;
    aR1 = aval ? *(const float4*)(Aptr + 4) : fz;
    if (BT) {
        bR0 = bval ? *(const float4*)(Bptr)     : fz;
        bR1 = bval ? *(const float4*)(Bptr + 4) : fz;
    } else {
        bR0 = bval ? *(const float4*)(Bptr + (size_t)bkk * Nc)     : fz;
        bR1 = bval ? *(const float4*)(Bptr + (size_t)bkk * Nc + 4) : fz;
    }

    float acc[4][4][4];
#pragma unroll
    for (int i = 0; i < 4; i++)
#pragma unroll
        for (int j = 0; j < 4; j++)
#pragma unroll
            for (int r = 0; r < 4; r++) acc[i][j][r] = 0.f;

    for (int k0 = 0; k0 < K; k0 += 16) {
        {
            uint32_t* ap = &As[ar * LDW + akk];
            ap[0] = f2tf(aR0.x); ap[1] = f2tf(aR0.y); ap[2] = f2tf(aR0.z); ap[3] = f2tf(aR0.w);
            ap[4] = f2tf(aR1.x); ap[5] = f2tf(aR1.y); ap[6] = f2tf(aR1.z); ap[7] = f2tf(aR1.w);
            if (BT) {
                uint32_t* bp = &Bs[br * LDW + bkk];
                bp[0] = f2tf(bR0.x); bp[1] = f2tf(bR0.y); bp[2] = f2tf(bR0.z); bp[3] = f2tf(bR0.w);
                bp[4] = f2tf(bR1.x); bp[5] = f2tf(bR1.y); bp[6] = f2tf(bR1.z); bp[7] = f2tf(bR1.w);
            } else {
                float v[8] = {bR0.x, bR0.y, bR0.z, bR0.w, bR1.x, bR1.y, bR1.z, bR1.w};
#pragma unroll
                for (int q = 0; q < 8; q++) Bs[(br + q) * LDW + bkk] = f2tf(v[q]);
            }
        }
        __syncthreads();

        const int kn = k0 + 16;
        if (kn < K) {
            aR0 = aval ? *(const float4*)(Aptr + kn)     : fz;
            aR1 = aval ? *(const float4*)(Aptr + kn + 4) : fz;
            if (BT) {
                bR0 = bval ? *(const float4*)(Bptr + kn)     : fz;
                bR1 = bval ? *(const float4*)(Bptr + kn + 4) : fz;
            } else {
                bR0 = bval ? *(const float4*)(Bptr + (size_t)(kn + bkk) * Nc)     : fz;
                bR1 = bval ? *(const float4*)(Bptr + (size_t)(kn + bkk) * Nc + 4) : fz;
            }
        }

#pragma unroll
        for (int ks = 0; ks < 16; ks += 8) {
            uint32_t af[4][4], bf[4][2];
#pragma unroll
            for (int mt = 0; mt < 4; mt++) {
                int r = mBase + mt * 16 + lq;
                int c = ks + lr;
                af[mt][0] = As[r * LDW + c];
                af[mt][1] = As[(r + 8) * LDW + c];
                af[mt][2] = As[r * LDW + c + 4];
                af[mt][3] = As[(r + 8) * LDW + c + 4];
            }
#pragma unroll
            for (int nt = 0; nt < 4; nt++) {
                int n = nBase + nt * 8 + lq;
                bf[nt][0] = Bs[n * LDW + ks + lr];
                bf[nt][1] = Bs[n * LDW + ks + 4 + lr];
            }
#pragma unroll
            for (int mt = 0; mt < 4; mt++)
#pragma unroll
                for (int nt = 0; nt < 4; nt++)
                    MMA_TF32(acc[mt][nt], af[mt], bf[nt]);
        }
        __syncthreads();
    }

    if (MODE == 0) {
#pragma unroll
        for (int mt = 0; mt < 4; mt++) {
            int r0 = rowBase + mBase + mt * 16 + lq;
#pragma unroll
            for (int nt = 0; nt < 4; nt++) {
                int gc = colBase + nBase + nt * 8 + 2 * lr;
                if (gc < Nc) {
                    float* p0 = C + (size_t)r0 * Nc + gc;
                    float* p1 = C + (size_t)(r0 + 8) * Nc + gc;
                    p0[0] = acc[mt][nt][0]; p0[1] = acc[mt][nt][1];
                    p1[0] = acc[mt][nt][2]; p1[1] = acc[mt][nt][3];
                    if (Cb) {
                        ((uint32_t*)Cb)[((size_t)r0 * Nc + gc) >> 1] =
                            packbf(acc[mt][nt][0], acc[mt][nt][1]);
                        ((uint32_t*)Cb)[((size_t)(r0 + 8) * Nc + gc) >> 1] =
                            packbf(acc[mt][nt][2], acc[mt][nt][3]);
                    }
                }
            }
        }
    } else {
        float rs[4][2];
#pragma unroll
        for (int mt = 0; mt < 4; mt++) { rs[mt][0] = 0.f; rs[mt][1] = 0.f; }
#pragma unroll
        for (int nt = 0; nt < 4; nt++) {
            int gc = colBase + nBase + nt * 8 + 2 * lr;
            bool v0 = gc < Nc, v1 = (gc + 1) < Nc;
            float bv0 = v0 ? bias[gc] : 0.f;
            float bv1 = v1 ? bias[gc + 1] : 0.f;
#pragma unroll
            for (int mt = 0; mt < 4; mt++) {
                if (v0) {
                    rs[mt][0] += __expf(acc[mt][nt][0] + bv0);
                    rs[mt][1] += __expf(acc[mt][nt][2] + bv0);
                }
                if (v1) {
                    rs[mt][0] += __expf(acc[mt][nt][1] + bv1);
                    rs[mt][1] += __expf(acc[mt][nt][3] + bv1);
                }
            }
        }
#pragma unroll
        for (int mt = 0; mt < 4; mt++)
#pragma unroll
            for (int h = 0; h < 2; h++) {
                float v = rs[mt][h];
                v += __shfl_xor_sync(0xffffffffu, v, 1);
                v += __shfl_xor_sync(0xffffffffu, v, 2);
                if (lr == 0)
                    atomicAdd(&rsum[mBase + mt * 16 + h * 8 + lq], v);
            }
        __syncthreads();
        if (tid < 128) {
            int gr = rowBase + tid;
            if (gr < count) {
                int n = rowmap ? rowmap[gr] : gr;
                atomicAdd(&Ssum[n], rsum[tid]);
            }
        }
    }
}

// ---------------- prep: init + classify (single block) ---------------------
__global__ void prep_kernel(const int* __restrict__ target) {
    int i = threadIdx.x;
    g_S0[i] = 0.f; g_St[i] = 0.f;
    if (i < 3) g_count[i] = 0;
    __syncthreads();
    int t = target[i];
    int c = (t < 20000) ? 0 : (t < 40000) ? 1 : (t < 200000) ? 2 : 3;
    g_cluster[i] = c;
    if (c > 0) {
        int idx = atomicAdd(&g_count[c - 1], 1);
        g_rowlist[(c - 1) * NROWS + idx] = i;
    }
}

// ---------------- bufprep: wcat concat + w->bf16 conversions ----------------
__global__ void bufprep_kernel(
    const float4* __restrict__ p0, const float4* __restrict__ p1,
    const float4* __restrict__ p2, const float4* __restrict__ p3,
    const float4* __restrict__ w0, const float4* __restrict__ w1,
    const float4* __restrict__ w2)
{
    const int T0 = 348160;            // wcat: 1024*1360/4
    const int T1 = T0 + 5120768;      // w0b:  20003*1024/4
    const int T2 = T1 + 1280000;      // w1b:  20000*256/4
    const int T3 = T2 + 2560000;      // w2b:  160000*64/4
    for (int i = blockIdx.x * blockDim.x + threadIdx.x; i < T3;
         i += gridDim.x * blockDim.x) {
        if (i < T0) {
            int k = i / 340, c4 = i - k * 340;
            float4 v;
            if (c4 < 256)      v = p0[k * 256 + c4];
            else if (c4 < 320) v = p1[k * 64 + (c4 - 256)];
            else if (c4 < 336) v = p2[k * 16 + (c4 - 320)];
            else               v = p3[k * 4 + (c4 - 336)];
            ((float4*)g_wcat)[i] = v;
        } else if (i < T1) {
            int j = i - T0; float4 v = w0[j];
            ((uint2*)g_w0b)[j] = make_uint2(packbf(v.x, v.y), packbf(v.z, v.w));
        } else if (i < T2) {
            int j = i - T1; float4 v = w1[j];
            ((uint2*)g_w1b)[j] = make_uint2(packbf(v.x, v.y), packbf(v.z, v.w));
        } else {
            int j = i - T2; float4 v = w2[j];
            ((uint2*)g_w2b)[j] = make_uint2(packbf(v.x, v.y), packbf(v.z, v.w));
        }
    }
}

// ---------------- merged gathers (one warp per row) -------------------------
__global__ void gather_kernel(
    const float* __restrict__ w0, const float* __restrict__ b0,
    const float* __restrict__ w1, const float* __restrict__ b1,
    const float* __restrict__ w2, const float* __restrict__ b2,
    const float* __restrict__ w3, const float* __restrict__ b3,
    const int* __restrict__ target)
{
    int gw = (blockIdx.x * blockDim.x + threadIdx.x) >> 5;
    int lane = threadIdx.x & 31;
    if (gw < NROWS) {
        int c = g_cluster[gw];
        int col = (c == 0) ? target[gw] : (HEAD_SIZE - c);
        const float4* pr = (const float4*)(g_proj + (size_t)gw * PCW);
        const float4* wr = (const float4*)(w0 + (size_t)col * 1024);
        float s = 0.f;
        for (int i = lane; i < 256; i += 32) {
            float4 a = pr[i], b = wr[i];
            s += a.x * b.x + a.y * b.y + a.z * b.z + a.w * b.w;
        }
#pragma unroll
        for (int o = 16; o; o >>= 1) s += __shfl_down_sync(0xffffffffu, s, o);
        if (lane == 0) g_ghead[gw] = s + b0[col];
    } else if (gw < 2 * NROWS) {
        int w = gw - NROWS;
        int c = g_cluster[w];
        if (c == 0) return;
        const float* pr; const float* W; const float* bb; int K, off;
        if (c == 1)      { pr = g_proj + (size_t)w * PCW + 1024; W = w1; bb = b1; K = 256; off = 20000; }
        else if (c == 2) { pr = g_proj + (size_t)w * PCW + 1280; W = w2; bb = b2; K = 64;  off = 40000; }
        else             { pr = g_proj + (size_t)w * PCW + 1344; W = w3; bb = b3; K = 16;  off = 200000; }
        int ti = target[w] - off;
        float s = 0.f;
        for (int k = lane; k < K; k += 32) s += pr[k] * W[(size_t)ti * K + k];
#pragma unroll
        for (int o = 16; o; o >>= 1) s += __shfl_down_sync(0xffffffffu, s, o);
        if (lane == 0) g_gtail[w] = s + bb[ti];
    }
}

__global__ void combine_kernel(float* __restrict__ out, int n) {
    int i = blockIdx.x * blockDim.x + threadIdx.x;
    if (i >= n) return;
    float v = logf(g_S0[i]) - g_ghead[i];
    if (g_cluster[i] > 0) v += logf(g_St[i]) - g_gtail[i];
    out[i] = v;
}

// ---------------- launch ----------------------------------------------------
extern "C" void kernel_launch(void* const* d_in, const int* in_sizes, int n_in,
                              void* d_out, int out_size) {
    const float* hidden = (const float*)d_in[0];
    const int*   target = (const int*)d_in[1];
    const float* w0 = (const float*)d_in[2];
    const float* b0 = (const float*)d_in[3];
    const float* p0 = (const float*)d_in[4];
    const float* w1 = (const float*)d_in[5];
    const float* b1 = (const float*)d_in[6];
    const float* p1 = (const float*)d_in[7];
    const float* w2 = (const float*)d_in[8];
    const float* b2 = (const float*)d_in[9];
    const float* p2 = (const float*)d_in[10];
    const float* w3 = (const float*)d_in[11];
    const float* b3 = (const float*)d_in[12];
    const float* p3 = (const float*)d_in[13];
    float* out = (float*)d_out;

    float *wcat, *proj, *S0, *St;
    __nv_bfloat16 *projb, *w0b, *w1b, *w2b;
    int *rowlist, *cnt;
    cudaGetSymbolAddress((void**)&wcat, g_wcat);
    cudaGetSymbolAddress((void**)&proj, g_proj);
    cudaGetSymbolAddress((void**)&projb, g_projb);
    cudaGetSymbolAddress((void**)&w0b, g_w0b);
    cudaGetSymbolAddress((void**)&w1b, g_w1b);
    cudaGetSymbolAddress((void**)&w2b, g_w2b);
    cudaGetSymbolAddress((void**)&S0, g_S0);
    cudaGetSymbolAddress((void**)&St, g_St);
    cudaGetSymbolAddress((void**)&rowlist, g_rowlist);
    cudaGetSymbolAddress((void**)&cnt, g_count);

    const int N = NROWS;

    prep_kernel<<<1, 1024>>>(target);
    bufprep_kernel<<<2048, 256>>>((const float4*)p0, (const float4*)p1,
                                  (const float4*)p2, (const float4*)p3,
                                  (const float4*)w0, (const float4*)w1,
                                  (const float4*)w2);

    // proj_cat = hidden @ wcat  (tf32 NN, fp32 + bf16 outputs)
    mma_gemm<0, 0><<<dim3(11, 8, 1), 256>>>(
        hidden, 1024, wcat, nullptr, proj, projb, nullptr,
        N, PCW, 1024, nullptr, nullptr);

    // head: bf16 sum-exp over 20003 cols, all rows
    bf16_sumexp<<<dim3(157, 8, 1), 256>>>(
        projb, PCW, w0b, b0, S0, N, HEAD_SIZE, 1024, nullptr, nullptr);

    // tails (row-compacted)
    bf16_sumexp<<<dim3(157, 8, 1), 256>>>(
        projb + 1024, PCW, w1b, b1, St, N, 20000, 256,
        rowlist + 0 * NROWS, cnt + 0);
    bf16_sumexp<<<dim3(1250, 8, 1), 256>>>(
        projb + 1280, PCW, w2b, b2, St, N, 160000, 64,
        rowlist + 1 * NROWS, cnt + 1);
    mma_gemm<1, 1><<<dim3(530, 8, 1), 256>>>(
        proj + 1344, PCW, w3, b3, nullptr, nullptr, St,
        N, 67735, 16, rowlist + 2 * NROWS, cnt + 2);

    gather_kernel<<<256, 256>>>(w0, b0, w1, b1, w2, b2, w3, b3, target);
    combine_kernel<<<(N + 255) / 256, 256>>>(out, N);
}

// round 8
// speedup vs baseline: 4.0224x; 1.0901x over previous
#include <cuda_runtime.h>
#include <cuda_bf16.h>
#include <math.h>
#include <stdint.h>

// ---------------------------------------------------------------------------
// AdaptiveLogSoftmax NLL.
//   prep:    concat proj weights -> wcat; convert w0/w1/w2 -> e4m3 (x8 scale)
//   proj:    proj_cat = hidden @ wcat (tf32 mma.sync), fp32 + fp8(x8) outputs
//   head/t1/t2: fp8 m16n8k32 mma.sync, fp32 accum, fused sum-exp epilogue
//              (logits carried x64; epilogue rescales by 1/64)
//   tail3:   tf32 mma.sync sum-exp (K=16)
//   gather:  exact fp32 dot for target logits
// NOTE: tcgen05 is ptxas-rejected at this harness's PTX target (sm_103 plain);
// fp8 mma.sync fragments are byte-identical to bf16 k16 fragments, so the
// proven R6 ldmatrix/LDW-20 structure is reused unchanged.
// ---------------------------------------------------------------------------

#define NROWS 1024
#define HEAD_SIZE 20003
#define PCW 1360
#define INV64 0.015625f

__device__ __align__(16) float    g_wcat[1024 * PCW];
__device__ __align__(16) float    g_proj[NROWS * PCW];      // fp32 projections
__device__ __align__(16) uint8_t  g_proj8[NROWS * PCW];     // e4m3, x8
__device__ __align__(16) uint8_t  g_w0b[20003 * 1024];      // e4m3, x8
__device__ __align__(16) uint8_t  g_w1b[20000 * 256];
__device__ __align__(16) uint8_t  g_w2b[160000 * 64];
__device__ float g_S0[NROWS];
__device__ float g_St[NROWS];
__device__ float g_ghead[NROWS];
__device__ float g_gtail[NROWS];
__device__ int   g_rowlist[3 * NROWS];
__device__ int   g_count[3];
__device__ int   g_cluster[NROWS];

// ---------------- helpers ---------------------------------------------------
__device__ __forceinline__ uint32_t f2tf(float f) {
    uint32_t r;
    asm("cvt.rna.tf32.f32 %0, %1;" : "=r"(r) : "f"(f));
    return r;
}
__device__ __forceinline__ uint16_t pack_e4m3(float lo, float hi) {
    uint16_t r;
    asm("cvt.rn.satfinite.e4m3x2.f32 %0, %1, %2;" : "=h"(r) : "f"(hi), "f"(lo));
    return r;
}
__device__ __forceinline__ uint32_t pack4_e4m3_x8(float4 v) {
    uint16_t l = pack_e4m3(v.x * 8.f, v.y * 8.f);
    uint16_t h = pack_e4m3(v.z * 8.f, v.w * 8.f);
    return (uint32_t)l | ((uint32_t)h << 16);
}

#define MMA_TF32(c, a, b)                                                     \
    asm volatile(                                                             \
        "mma.sync.aligned.m16n8k8.row.col.f32.tf32.tf32.f32 "                 \
        "{%0,%1,%2,%3},{%4,%5,%6,%7},{%8,%9},{%0,%1,%2,%3};"                  \
        : "+f"(c[0]), "+f"(c[1]), "+f"(c[2]), "+f"(c[3])                      \
        : "r"(a[0]), "r"(a[1]), "r"(a[2]), "r"(a[3]), "r"(b[0]), "r"(b[1]))

#define MMA_FP8(c, a0, a1, a2, a3, b0, b1)                                    \
    asm volatile(                                                             \
        "mma.sync.aligned.m16n8k32.row.col.f32.e4m3.e4m3.f32 "                \
        "{%0,%1,%2,%3},{%4,%5,%6,%7},{%8,%9},{%0,%1,%2,%3};"                  \
        : "+f"(c[0]), "+f"(c[1]), "+f"(c[2]), "+f"(c[3])                      \
        : "r"(a0), "r"(a1), "r"(a2), "r"(a3), "r"(b0), "r"(b1))

#define LDSM4(r0, r1, r2, r3, addr)                                           \
    asm volatile("ldmatrix.sync.aligned.m8n8.x4.shared.b16 {%0,%1,%2,%3}, [%4];" \
        : "=r"(r0), "=r"(r1), "=r"(r2), "=r"(r3) : "r"(addr))

#define LDW 20   // smem word stride per row: 16 data words (64B) + 4 pad

// ===========================================================================
// fp8 GEMM + fused sum-exp.  A: [., lda] e4m3 row-major (byte stride,
// rowmap-indirected). B: [Nc, K] e4m3 row-major. Tile 128x128xK64.
// 256 threads, 8 warps (2Mx4N, 64x32 per warp). Operands carry x8 scale
// each -> acc is 64x the true logit; epilogue applies 1/64.
// ===========================================================================
__global__ void __launch_bounds__(256, 2) fp8_sumexp(
    const uint8_t* __restrict__ A, int lda,
    const uint8_t* __restrict__ B,
    const float* __restrict__ bias, float* __restrict__ Ssum,
    int M, int Nc, int K,
    const int* __restrict__ rowmap, const int* __restrict__ countPtr)
{
    __shared__ __align__(16) uint32_t As[128 * LDW];
    __shared__ __align__(16) uint32_t Bs[128 * LDW];
    __shared__ float rsum[128];

    const int count = countPtr ? *countPtr : M;
    const int rowBase = blockIdx.y * 128;
    if (rowBase >= count) return;
    const int colBase = blockIdx.x * 128;

    const int tid  = threadIdx.x;
    const int lane = tid & 31;
    const int wid  = tid >> 5;
    const int mBase = (wid & 1) * 64;
    const int nBase = (wid >> 1) * 32;
    const int lq = lane >> 2;
    const int lr = lane & 3;

    if (tid < 128) rsum[tid] = 0.f;

    // loaders: row = tid/2, half = 32 bytes (2 uint4) of the 64B k-chunk
    const int ar   = tid >> 1;
    const int half = tid & 1;
    const int gA   = rowBase + ar;
    const bool aval = (gA < count);
    const int arow = aval ? (rowmap ? rowmap[gA] : gA) : 0;
    const uint8_t* Ag = A + (size_t)arow * lda + half * 32;
    int gB = colBase + ar; if (gB >= Nc) gB = Nc - 1;
    const uint8_t* Bg = B + (size_t)gB * K + half * 32;

    uint4 aV0, aV1, bV0, bV1;
    aV0 = ((const uint4*)Ag)[0]; aV1 = ((const uint4*)Ag)[1];
    bV0 = ((const uint4*)Bg)[0]; bV1 = ((const uint4*)Bg)[1];

    const uint32_t asb = (uint32_t)__cvta_generic_to_shared(As);
    const uint32_t bsb = (uint32_t)__cvta_generic_to_shared(Bs);
    const uint32_t aBase = asb + ((mBase + (lane & 15)) * LDW + (lane >> 4) * 4) * 4;
    const uint32_t bBase = bsb + ((nBase + lane) * LDW) * 4;

    float acc[4][4][4];
#pragma unroll
    for (int i = 0; i < 4; i++)
#pragma unroll
        for (int j = 0; j < 4; j++)
#pragma unroll
            for (int r = 0; r < 4; r++) acc[i][j][r] = 0.f;

    for (int k0 = 0; k0 < K; k0 += 64) {
        {
            uint4* ap = (uint4*)&As[ar * LDW + half * 8];
            uint4* bp = (uint4*)&Bs[ar * LDW + half * 8];
            ap[0] = aV0; ap[1] = aV1;
            bp[0] = bV0; bp[1] = bV1;
        }
        __syncthreads();

        const int kn = k0 + 64;
        if (kn < K) {
            aV0 = ((const uint4*)(Ag + kn))[0];
            aV1 = ((const uint4*)(Ag + kn))[1];
            bV0 = ((const uint4*)(Bg + kn))[0];
            bV1 = ((const uint4*)(Bg + kn))[1];
        }

#pragma unroll
        for (int c = 0; c < 2; ++c) {   // two k32 steps (32B each)
            uint32_t af[4][4], b0r[4], b1r[4];
            LDSM4(b0r[0], b0r[1], b0r[2], b0r[3], bBase + c * 32);
            LDSM4(b1r[0], b1r[1], b1r[2], b1r[3], bBase + c * 32 + 16);
#pragma unroll
            for (int mt = 0; mt < 4; mt++)
                LDSM4(af[mt][0], af[mt][1], af[mt][2], af[mt][3],
                      aBase + mt * (16 * LDW * 4) + c * 32);
#pragma unroll
            for (int mt = 0; mt < 4; mt++)
#pragma unroll
                for (int nt = 0; nt < 4; nt++)
                    MMA_FP8(acc[mt][nt],
                            af[mt][0], af[mt][1], af[mt][2], af[mt][3],
                            b0r[nt], b1r[nt]);
        }
        __syncthreads();
    }

    // fused sum-exp epilogue (rescale x64 logits by 1/64)
    float rs[4][2];
#pragma unroll
    for (int mt = 0; mt < 4; mt++) { rs[mt][0] = 0.f; rs[mt][1] = 0.f; }
#pragma unroll
    for (int nt = 0; nt < 4; nt++) {
        int gc = colBase + nBase + nt * 8 + 2 * lr;
        bool v0 = gc < Nc, v1 = (gc + 1) < Nc;
        float bv0 = v0 ? bias[gc] : 0.f;
        float bv1 = v1 ? bias[gc + 1] : 0.f;
#pragma unroll
        for (int mt = 0; mt < 4; mt++) {
            if (v0) {
                rs[mt][0] += __expf(fmaf(acc[mt][nt][0], INV64, bv0));
                rs[mt][1] += __expf(fmaf(acc[mt][nt][2], INV64, bv0));
            }
            if (v1) {
                rs[mt][0] += __expf(fmaf(acc[mt][nt][1], INV64, bv1));
                rs[mt][1] += __expf(fmaf(acc[mt][nt][3], INV64, bv1));
            }
        }
    }
#pragma unroll
    for (int mt = 0; mt < 4; mt++)
#pragma unroll
        for (int h = 0; h < 2; h++) {
            float v = rs[mt][h];
            v += __shfl_xor_sync(0xffffffffu, v, 1);
            v += __shfl_xor_sync(0xffffffffu, v, 2);
            if (lr == 0)
                atomicAdd(&rsum[mBase + mt * 16 + h * 8 + lq], v);
        }
    __syncthreads();
    if (tid < 128) {
        int gr = rowBase + tid;
        if (gr < count) {
            int n = rowmap ? rowmap[gr] : gr;
            atomicAdd(&Ssum[n], rsum[tid]);
        }
    }
}

// ===========================================================================
// tf32 mma.sync GEMM. MODE 0: store C fp32 (+ optional fp8 x8 copy).
// MODE 1: sum-exp. BT=1: B [Nc,K]; BT=0: B [K,Nc].
// ===========================================================================
template <int MODE, int BT>
__global__ void __launch_bounds__(256, 2) mma_gemm(
    const float* __restrict__ A, int lda, const float* __restrict__ B,
    const float* __restrict__ bias, float* __restrict__ C,
    uint8_t* __restrict__ C8,
    float* __restrict__ Ssum, int M, int Nc, int K,
    const int* __restrict__ rowmap, const int* __restrict__ countPtr)
{
    __shared__ uint32_t As[128 * LDW];
    __shared__ uint32_t Bs[128 * LDW];
    __shared__ float rsum[128];

    const int count = countPtr ? *countPtr : M;
    const int rowBase = blockIdx.y * 128;
    if (rowBase >= count) return;
    const int colBase = blockIdx.x * 128;

    const int tid  = threadIdx.x;
    const int lane = tid & 31;
    const int wid  = tid >> 5;
    const int mBase = (wid & 1) * 64;
    const int nBase = (wid >> 1) * 32;
    const int lq = lane >> 2;
    const int lr = lane & 3;

    if (MODE == 1 && tid < 128) rsum[tid] = 0.f;

    const int ar  = tid >> 1;
    const int akk = (tid & 1) * 8;
    const int gA  = rowBase + ar;
    const bool aval = (gA < count);
    const int arow = aval ? (rowmap ? rowmap[gA] : gA) : 0;
    const float* Aptr = A + (size_t)arow * lda + akk;

    int br, bkk; bool bval; const float* Bptr;
    if (BT) {
        br  = tid >> 1;
        bkk = (tid & 1) * 8;
        bval = (colBase + br) < Nc;
        Bptr = B + (size_t)(bval ? colBase + br : 0) * K + bkk;
    } else {
        bkk = tid >> 4;
        br  = (tid & 15) * 8;
        bval = (colBase + br) < Nc;
        Bptr = B + colBase + (bval ? br : 0);
    }

    const float4 fz = make_float4(0.f, 0.f, 0.f, 0.f);
    float4 aR0, aR1, bR0, bR1;
    aR0 = aval ? *(const float4*)(Aptr)     : fz;
    aR1 = aval ? *(const float4*)(Aptr + 4) : fz;
    if (BT) {
        bR0 = bval ? *(const float4*)(Bptr)     : fz;
        bR1 = bval ? *(const float4*)(Bptr + 4) : fz;
    } else {
        bR0 = bval ? *(const float4*)(Bptr + (size_t)bkk * Nc)     : fz;
        bR1 = bval ? *(const float4*)(Bptr + (size_t)bkk * Nc + 4) : fz;
    }

    float acc[4][4][4];
#pragma unroll
    for (int i = 0; i < 4; i++)
#pragma unroll
        for (int j = 0; j < 4; j++)
#pragma unroll
            for (int r = 0; r < 4; r++) acc[i][j][r] = 0.f;

    for (int k0 = 0; k0 < K; k0 += 16) {
        {
            uint32_t* ap = &As[ar * LDW + akk];
            ap[0] = f2tf(aR0.x); ap[1] = f2tf(aR0.y); ap[2] = f2tf(aR0.z); ap[3] = f2tf(aR0.w);
            ap[4] = f2tf(aR1.x); ap[5] = f2tf(aR1.y); ap[6] = f2tf(aR1.z); ap[7] = f2tf(aR1.w);
            if (BT) {
                uint32_t* bp = &Bs[br * LDW + bkk];
                bp[0] = f2tf(bR0.x); bp[1] = f2tf(bR0.y); bp[2] = f2tf(bR0.z); bp[3] = f2tf(bR0.w);
                bp[4] = f2tf(bR1.x); bp[5] = f2tf(bR1.y); bp[6] = f2tf(bR1.z); bp[7] = f2tf(bR1.w);
            } else {
                float v[8] = {bR0.x, bR0.y, bR0.z, bR0.w, bR1.x, bR1.y, bR1.z, bR1.w};
#pragma unroll
                for (int q = 0; q < 8; q++) Bs[(br + q) * LDW + bkk] = f2tf(v[q]);
            }
        }
        __syncthreads();

        const int kn = k0 + 16;
        if (kn < K) {
            aR0 = aval ? *(const float4*)(Aptr + kn)     : fz;
            aR1 = aval ? *(const float4*)(Aptr + kn + 4) : fz;
            if (BT) {
                bR0 = bval ? *(const float4*)(Bptr + kn)     : fz;
                bR1 = bval ? *(const float4*)(Bptr + kn + 4) : fz;
            } else {
                bR0 = bval ? *(const float4*)(Bptr + (size_t)(kn + bkk) * Nc)     : fz;
                bR1 = bval ? *(const float4*)(Bptr + (size_t)(kn + bkk) * Nc + 4) : fz;
            }
        }

#pragma unroll
        for (int ks = 0; ks < 16; ks += 8) {
            uint32_t af[4][4], bf[4][2];
#pragma unroll
            for (int mt = 0; mt < 4; mt++) {
                int r = mBase + mt * 16 + lq;
                int c = ks + lr;
                af[mt][0] = As[r * LDW + c];
                af[mt][1] = As[(r + 8) * LDW + c];
                af[mt][2] = As[r * LDW + c + 4];
                af[mt][3] = As[(r + 8) * LDW + c + 4];
            }
#pragma unroll
            for (int nt = 0; nt < 4; nt++) {
                int n = nBase + nt * 8 + lq;
                bf[nt][0] = Bs[n * LDW + ks + lr];
                bf[nt][1] = Bs[n * LDW + ks + 4 + lr];
            }
#pragma unroll
            for (int mt = 0; mt < 4; mt++)
#pragma unroll
                for (int nt = 0; nt < 4; nt++)
                    MMA_TF32(acc[mt][nt], af[mt], bf[nt]);
        }
        __syncthreads();
    }

    if (MODE == 0) {
#pragma unroll
        for (int mt = 0; mt < 4; mt++) {
            int r0 = rowBase + mBase + mt * 16 + lq;
#pragma unroll
            for (int nt = 0; nt < 4; nt++) {
                int gc = colBase + nBase + nt * 8 + 2 * lr;
                if (gc < Nc) {
                    float* p0 = C + (size_t)r0 * Nc + gc;
                    float* p1 = C + (size_t)(r0 + 8) * Nc + gc;
                    p0[0] = acc[mt][nt][0]; p0[1] = acc[mt][nt][1];
                    p1[0] = acc[mt][nt][2]; p1[1] = acc[mt][nt][3];
                    if (C8) {
                        ((uint16_t*)C8)[((size_t)r0 * Nc + gc) >> 1] =
                            pack_e4m3(acc[mt][nt][0] * 8.f, acc[mt][nt][1] * 8.f);
                        ((uint16_t*)C8)[((size_t)(r0 + 8) * Nc + gc) >> 1] =
                            pack_e4m3(acc[mt][nt][2] * 8.f, acc[mt][nt][3] * 8.f);
                    }
                }
            }
        }
    } else {
        float rs[4][2];
#pragma unroll
        for (int mt = 0; mt < 4; mt++) { rs[mt][0] = 0.f; rs[mt][1] = 0.f; }
#pragma unroll
        for (int nt = 0; nt < 4; nt++) {
            int gc = colBase + nBase + nt * 8 + 2 * lr;
            bool v0 = gc < Nc, v1 = (gc + 1) < Nc;
            float bv0 = v0 ? bias[gc] : 0.f;
            float bv1 = v1 ? bias[gc + 1] : 0.f;
#pragma unroll
            for (int mt = 0; mt < 4; mt++) {
                if (v0) {
                    rs[mt][0] += __expf(acc[mt][nt][0] + bv0);
                    rs[mt][1] += __expf(acc[mt][nt][2] + bv0);
                }
                if (v1) {
                    rs[mt][0] += __expf(acc[mt][nt][1] + bv1);
                    rs[mt][1] += __expf(acc[mt][nt][3] + bv1);
                }
            }
        }
#pragma unroll
        for (int mt = 0; mt < 4; mt++)
#pragma unroll
            for (int h = 0; h < 2; h++) {
                float v = rs[mt][h];
                v += __shfl_xor_sync(0xffffffffu, v, 1);
                v += __shfl_xor_sync(0xffffffffu, v, 2);
                if (lr == 0)
                    atomicAdd(&rsum[mBase + mt * 16 + h * 8 + lq], v);
            }
        __syncthreads();
        if (tid < 128) {
            int gr = rowBase + tid;
            if (gr < count) {
                int n = rowmap ? rowmap[gr] : gr;
                atomicAdd(&Ssum[n], rsum[tid]);
            }
        }
    }
}

// ---------------- prep / bufprep / gather / combine -------------------------
__global__ void prep_kernel(const int* __restrict__ target) {
    int i = threadIdx.x;
    g_S0[i] = 0.f; g_St[i] = 0.f;
    if (i < 3) g_count[i] = 0;
    __syncthreads();
    int t = target[i];
    int c = (t < 20000) ? 0 : (t < 40000) ? 1 : (t < 200000) ? 2 : 3;
    g_cluster[i] = c;
    if (c > 0) {
        int idx = atomicAdd(&g_count[c - 1], 1);
        g_rowlist[(c - 1) * NROWS + idx] = i;
    }
}

__global__ void bufprep_kernel(
    const float4* __restrict__ p0, const float4* __restrict__ p1,
    const float4* __restrict__ p2, const float4* __restrict__ p3,
    const float4* __restrict__ w0, const float4* __restrict__ w1,
    const float4* __restrict__ w2)
{
    const int T0 = 348160;            // wcat: 1024*1360/4
    const int T1 = T0 + 5120768;      // w0:   20003*1024/4
    const int T2 = T1 + 1280000;      // w1:   20000*256/4
    const int T3 = T2 + 2560000;      // w2:   160000*64/4
    for (int i = blockIdx.x * blockDim.x + threadIdx.x; i < T3;
         i += gridDim.x * blockDim.x) {
        if (i < T0) {
            int k = i / 340, c4 = i - k * 340;
            float4 v;
            if (c4 < 256)      v = p0[k * 256 + c4];
            else if (c4 < 320) v = p1[k * 64 + (c4 - 256)];
            else if (c4 < 336) v = p2[k * 16 + (c4 - 320)];
            else               v = p3[k * 4 + (c4 - 336)];
            ((float4*)g_wcat)[i] = v;
        } else if (i < T1) {
            int j = i - T0;
            ((uint32_t*)g_w0b)[j] = pack4_e4m3_x8(w0[j]);
        } else if (i < T2) {
            int j = i - T1;
            ((uint32_t*)g_w1b)[j] = pack4_e4m3_x8(w1[j]);
        } else {
            int j = i - T2;
            ((uint32_t*)g_w2b)[j] = pack4_e4m3_x8(w2[j]);
        }
    }
}

__global__ void gather_kernel(
    const float* __restrict__ w0, const float* __restrict__ b0,
    const float* __restrict__ w1, const float* __restrict__ b1,
    const float* __restrict__ w2, const float* __restrict__ b2,
    const float* __restrict__ w3, const float* __restrict__ b3,
    const int* __restrict__ target)
{
    int gw = (blockIdx.x * blockDim.x + threadIdx.x) >> 5;
    int lane = threadIdx.x & 31;
    if (gw < NROWS) {
        int c = g_cluster[gw];
        int col = (c == 0) ? target[gw] : (HEAD_SIZE - c);
        const float4* pr = (const float4*)(g_proj + (size_t)gw * PCW);
        const float4* wr = (const float4*)(w0 + (size_t)col * 1024);
        float s = 0.f;
        for (int i = lane; i < 256; i += 32) {
            float4 a = pr[i], b = wr[i];
            s += a.x * b.x + a.y * b.y + a.z * b.z + a.w * b.w;
        }
#pragma unroll
        for (int o = 16; o; o >>= 1) s += __shfl_down_sync(0xffffffffu, s, o);
        if (lane == 0) g_ghead[gw] = s + b0[col];
    } else if (gw < 2 * NROWS) {
        int w = gw - NROWS;
        int c = g_cluster[w];
        if (c == 0) return;
        const float* pr; const float* W; const float* bb; int K, off;
        if (c == 1)      { pr = g_proj + (size_t)w * PCW + 1024; W = w1; bb = b1; K = 256; off = 20000; }
        else if (c == 2) { pr = g_proj + (size_t)w * PCW + 1280; W = w2; bb = b2; K = 64;  off = 40000; }
        else             { pr = g_proj + (size_t)w * PCW + 1344; W = w3; bb = b3; K = 16;  off = 200000; }
        int ti = target[w] - off;
        float s = 0.f;
        for (int k = lane; k < K; k += 32) s += pr[k] * W[(size_t)ti * K + k];
#pragma unroll
        for (int o = 16; o; o >>= 1) s += __shfl_down_sync(0xffffffffu, s, o);
        if (lane == 0) g_gtail[w] = s + bb[ti];
    }
}

__global__ void combine_kernel(float* __restrict__ out, int n) {
    int i = blockIdx.x * blockDim.x + threadIdx.x;
    if (i >= n) return;
    float v = logf(g_S0[i]) - g_ghead[i];
    if (g_cluster[i] > 0) v += logf(g_St[i]) - g_gtail[i];
    out[i] = v;
}

// ---------------- launch ----------------------------------------------------
extern "C" void kernel_launch(void* const* d_in, const int* in_sizes, int n_in,
                              void* d_out, int out_size) {
    const float* hidden = (const float*)d_in[0];
    const int*   target = (const int*)d_in[1];
    const float* w0 = (const float*)d_in[2];
    const float* b0 = (const float*)d_in[3];
    const float* p0 = (const float*)d_in[4];
    const float* w1 = (const float*)d_in[5];
    const float* b1 = (const float*)d_in[6];
    const float* p1 = (const float*)d_in[7];
    const float* w2 = (const float*)d_in[8];
    const float* b2 = (const float*)d_in[9];
    const float* p2 = (const float*)d_in[10];
    const float* w3 = (const float*)d_in[11];
    const float* b3 = (const float*)d_in[12];
    const float* p3 = (const float*)d_in[13];
    float* out = (float*)d_out;

    float *wcat, *proj, *S0, *St;
    uint8_t *proj8, *w0b, *w1b, *w2b;
    int *rowlist, *cnt;
    cudaGetSymbolAddress((void**)&wcat, g_wcat);
    cudaGetSymbolAddress((void**)&proj, g_proj);
    cudaGetSymbolAddress((void**)&proj8, g_proj8);
    cudaGetSymbolAddress((void**)&w0b, g_w0b);
    cudaGetSymbolAddress((void**)&w1b, g_w1b);
    cudaGetSymbolAddress((void**)&w2b, g_w2b);
    cudaGetSymbolAddress((void**)&S0, g_S0);
    cudaGetSymbolAddress((void**)&St, g_St);
    cudaGetSymbolAddress((void**)&rowlist, g_rowlist);
    cudaGetSymbolAddress((void**)&cnt, g_count);

    const int N = NROWS;

    prep_kernel<<<1, 1024>>>(target);
    bufprep_kernel<<<2048, 256>>>((const float4*)p0, (const float4*)p1,
                                  (const float4*)p2, (const float4*)p3,
                                  (const float4*)w0, (const float4*)w1,
                                  (const float4*)w2);

    // proj_cat = hidden @ wcat  (tf32 NN, fp32 + fp8 outputs)
    mma_gemm<0, 0><<<dim3(11, 8, 1), 256>>>(
        hidden, 1024, wcat, nullptr, proj, proj8, nullptr,
        N, PCW, 1024, nullptr, nullptr);

    // head: fp8 sum-exp over 20003 cols, all rows
    fp8_sumexp<<<dim3(157, 8, 1), 256>>>(
        proj8, PCW, w0b, b0, S0, N, HEAD_SIZE, 1024, nullptr, nullptr);

    // tails (row-compacted)
    fp8_sumexp<<<dim3(157, 8, 1), 256>>>(
        proj8 + 1024, PCW, w1b, b1, St, N, 20000, 256,
        rowlist + 0 * NROWS, cnt + 0);
    fp8_sumexp<<<dim3(1250, 8, 1), 256>>>(
        proj8 + 1280, PCW, w2b, b2, St, N, 160000, 64,
        rowlist + 1 * NROWS, cnt + 1);
    mma_gemm<1, 1><<<dim3(530, 8, 1), 256>>>(
        proj + 1344, PCW, w3, b3, nullptr, nullptr, St,
        N, 67735, 16, rowlist + 2 * NROWS, cnt + 2);

    gather_kernel<<<256, 256>>>(w0, b0, w1, b1, w2, b2, w3, b3, target);
    combine_kernel<<<(N + 255) / 256, 256>>>(out, N);
}

// round 9
// speedup vs baseline: 4.3897x; 1.0913x over previous
#include <cuda_runtime.h>
#include <cuda_bf16.h>
#include <math.h>
#include <stdint.h>

// ---------------------------------------------------------------------------
// AdaptiveLogSoftmax NLL.
//   prep:    concat proj weights -> wcat; convert w0/w1/w2 -> e4m3 (x8 scale)
//   proj:    proj_cat = hidden @ wcat (tf32 mma.sync), fp32 + fp8(x8) outputs
//   head/t1/t2: ONE merged fp8 m16n8k32 launch, double-buffered smem,
//              fused sum-exp epilogue (exp2-based; logits carried x64)
//   tail3:   tf32 mma.sync sum-exp (K=16)
//   gather:  exact fp32 dot for target logits
// ---------------------------------------------------------------------------

#define NROWS 1024
#define HEAD_SIZE 20003
#define PCW 1360
#define LOG2E 1.4426950408889634f
#define INV64_LOG2E (LOG2E / 64.f)

__device__ __align__(16) float    g_wcat[1024 * PCW];
__device__ __align__(16) float    g_proj[NROWS * PCW];
__device__ __align__(16) uint8_t  g_proj8[NROWS * PCW];
__device__ __align__(16) uint8_t  g_w0b[20003 * 1024];
__device__ __align__(16) uint8_t  g_w1b[20000 * 256];
__device__ __align__(16) uint8_t  g_w2b[160000 * 64];
__device__ float g_S0[NROWS];
__device__ float g_St[NROWS];
__device__ float g_ghead[NROWS];
__device__ float g_gtail[NROWS];
__device__ int   g_rowlist[3 * NROWS];
__device__ int   g_count[3];
__device__ int   g_cluster[NROWS];

// ---------------- helpers ---------------------------------------------------
__device__ __forceinline__ uint32_t f2tf(float f) {
    uint32_t r;
    asm("cvt.rna.tf32.f32 %0, %1;" : "=r"(r) : "f"(f));
    return r;
}
__device__ __forceinline__ uint16_t pack_e4m3(float lo, float hi) {
    uint16_t r;
    asm("cvt.rn.satfinite.e4m3x2.f32 %0, %1, %2;" : "=h"(r) : "f"(hi), "f"(lo));
    return r;
}
__device__ __forceinline__ uint32_t pack4_e4m3_x8(float4 v) {
    uint16_t l = pack_e4m3(v.x * 8.f, v.y * 8.f);
    uint16_t h = pack_e4m3(v.z * 8.f, v.w * 8.f);
    return (uint32_t)l | ((uint32_t)h << 16);
}

#define MMA_TF32(c, a, b)                                                     \
    asm volatile(                                                             \
        "mma.sync.aligned.m16n8k8.row.col.f32.tf32.tf32.f32 "                 \
        "{%0,%1,%2,%3},{%4,%5,%6,%7},{%8,%9},{%0,%1,%2,%3};"                  \
        : "+f"(c[0]), "+f"(c[1]), "+f"(c[2]), "+f"(c[3])                      \
        : "r"(a[0]), "r"(a[1]), "r"(a[2]), "r"(a[3]), "r"(b[0]), "r"(b[1]))

#define MMA_FP8(c, a0, a1, a2, a3, b0, b1)                                    \
    asm volatile(                                                             \
        "mma.sync.aligned.m16n8k32.row.col.f32.e4m3.e4m3.f32 "                \
        "{%0,%1,%2,%3},{%4,%5,%6,%7},{%8,%9},{%0,%1,%2,%3};"                  \
        : "+f"(c[0]), "+f"(c[1]), "+f"(c[2]), "+f"(c[3])                      \
        : "r"(a0), "r"(a1), "r"(a2), "r"(a3), "r"(b0), "r"(b1))

#define LDSM4(r0, r1, r2, r3, addr)                                           \
    asm volatile("ldmatrix.sync.aligned.m8n8.x4.shared.b16 {%0,%1,%2,%3}, [%4];" \
        : "=r"(r0), "=r"(r1), "=r"(r2), "=r"(r3) : "r"(addr))

#define LDW 20            // words per row: 16 data (64B) + 4 pad
#define BUFB (128 * LDW * 4)   // bytes per buffer per matrix

// ---------------- merged fp8 sum-exp problem table --------------------------
struct SEP {
    const uint8_t* A;
    const uint8_t* B;
    const float*   bias;
    float*         Ssum;
    int Nc, K, nx, base;
    const int* rowmap;
    const int* countPtr;
};
struct SEP3 { SEP p[3]; };

// ===========================================================================
// fp8 GEMM + fused sum-exp, double-buffered. Tile 128x128, K-chunks of 64.
// 256 threads, 8 warps (2Mx4N). Operands carry x8 each -> acc = 64x logit.
// Epilogue: exp2(acc * log2e/64 + bias*log2e).
// ===========================================================================
__global__ void __launch_bounds__(256, 2) fp8_sumexp_multi(SEP3 P)
{
    __shared__ __align__(16) uint32_t As[2][128 * LDW];
    __shared__ __align__(16) uint32_t Bs[2][128 * LDW];
    __shared__ float rsum[128];

    const int bx = blockIdx.x;
    const int pi = (bx >= P.p[1].base) + (bx >= P.p[2].base);
    const SEP sp = P.p[pi];
    const int local = bx - sp.base;
    const int tileX = local % sp.nx;
    const int tileY = local / sp.nx;

    const int count = sp.countPtr ? *sp.countPtr : NROWS;
    const int rowBase = tileY * 128;
    if (rowBase >= count) return;
    const int colBase = tileX * 128;
    const int Nc = sp.Nc, K = sp.K;

    const int tid  = threadIdx.x;
    const int lane = tid & 31;
    const int wid  = tid >> 5;
    const int mBase = (wid & 1) * 64;
    const int nBase = (wid >> 1) * 32;
    const int lq = lane >> 2;
    const int lr = lane & 3;

    if (tid < 128) rsum[tid] = 0.f;

    // loaders: row = tid/2, half = 32 bytes of the 64B k-chunk
    const int ar   = tid >> 1;
    const int half = tid & 1;
    const int gA   = rowBase + ar;
    const bool aval = (gA < count);
    const int arow = aval ? (sp.rowmap ? sp.rowmap[gA] : gA) : 0;
    const uint8_t* Ag = sp.A + (size_t)arow * PCW + half * 32;
    int gB = colBase + ar; if (gB >= Nc) gB = Nc - 1;
    const uint8_t* Bg = sp.B + (size_t)gB * K + half * 32;

    uint4 aV0, aV1, bV0, bV1;
    aV0 = ((const uint4*)Ag)[0]; aV1 = ((const uint4*)Ag)[1];
    bV0 = ((const uint4*)Bg)[0]; bV1 = ((const uint4*)Bg)[1];

    const uint32_t asb = (uint32_t)__cvta_generic_to_shared(&As[0][0]);
    const uint32_t bsb = (uint32_t)__cvta_generic_to_shared(&Bs[0][0]);
    const uint32_t aBase0 = asb + ((mBase + (lane & 15)) * LDW + (lane >> 4) * 4) * 4;
    const uint32_t bBase0 = bsb + ((nBase + lane) * LDW) * 4;

    float acc[4][4][4];
#pragma unroll
    for (int i = 0; i < 4; i++)
#pragma unroll
        for (int j = 0; j < 4; j++)
#pragma unroll
            for (int r = 0; r < 4; r++) acc[i][j][r] = 0.f;

    // store chunk 0 into buffer 0
    {
        uint4* ap = (uint4*)&As[0][ar * LDW + half * 8];
        uint4* bp = (uint4*)&Bs[0][ar * LDW + half * 8];
        ap[0] = aV0; ap[1] = aV1;
        bp[0] = bV0; bp[1] = bV1;
    }
    __syncthreads();

    const int nch = K >> 6;
    uint32_t buf = 0;

    for (int c = 0; c < nch; ++c) {
        const bool more = (c + 1 < nch);
        if (more) {
            const int kn = (c + 1) << 6;
            aV0 = ((const uint4*)(Ag + kn))[0];
            aV1 = ((const uint4*)(Ag + kn))[1];
            bV0 = ((const uint4*)(Bg + kn))[0];
            bV1 = ((const uint4*)(Bg + kn))[1];
        }

        const uint32_t aB = aBase0 + buf * BUFB;
        const uint32_t bB = bBase0 + buf * BUFB;
#pragma unroll
        for (int cc = 0; cc < 2; ++cc) {
            uint32_t af[4][4], b0r[4], b1r[4];
            LDSM4(b0r[0], b0r[1], b0r[2], b0r[3], bB + cc * 32);
            LDSM4(b1r[0], b1r[1], b1r[2], b1r[3], bB + cc * 32 + 16);
#pragma unroll
            for (int mt = 0; mt < 4; mt++)
                LDSM4(af[mt][0], af[mt][1], af[mt][2], af[mt][3],
                      aB + mt * (16 * LDW * 4) + cc * 32);
#pragma unroll
            for (int mt = 0; mt < 4; mt++)
#pragma unroll
                for (int nt = 0; nt < 4; nt++)
                    MMA_FP8(acc[mt][nt],
                            af[mt][0], af[mt][1], af[mt][2], af[mt][3],
                            b0r[nt], b1r[nt]);
        }

        if (more) {
            const uint32_t nb = buf ^ 1;
            uint4* ap = (uint4*)&As[nb][ar * LDW + half * 8];
            uint4* bp = (uint4*)&Bs[nb][ar * LDW + half * 8];
            ap[0] = aV0; ap[1] = aV1;
            bp[0] = bV0; bp[1] = bV1;
            __syncthreads();
            buf = nb;
        }
    }

    // fused sum-exp epilogue (exp2 with folded scales)
    float rs[4][2];
#pragma unroll
    for (int mt = 0; mt < 4; mt++) { rs[mt][0] = 0.f; rs[mt][1] = 0.f; }
#pragma unroll
    for (int nt = 0; nt < 4; nt++) {
        int gc = colBase + nBase + nt * 8 + 2 * lr;
        bool v0 = gc < Nc, v1 = (gc + 1) < Nc;
        float bv0 = v0 ? sp.bias[gc] * LOG2E : 0.f;
        float bv1 = v1 ? sp.bias[gc + 1] * LOG2E : 0.f;
#pragma unroll
        for (int mt = 0; mt < 4; mt++) {
            if (v0) {
                rs[mt][0] += exp2f(fmaf(acc[mt][nt][0], INV64_LOG2E, bv0));
                rs[mt][1] += exp2f(fmaf(acc[mt][nt][2], INV64_LOG2E, bv0));
            }
            if (v1) {
                rs[mt][0] += exp2f(fmaf(acc[mt][nt][1], INV64_LOG2E, bv1));
                rs[mt][1] += exp2f(fmaf(acc[mt][nt][3], INV64_LOG2E, bv1));
            }
        }
    }
#pragma unroll
    for (int mt = 0; mt < 4; mt++)
#pragma unroll
        for (int h = 0; h < 2; h++) {
            float v = rs[mt][h];
            v += __shfl_xor_sync(0xffffffffu, v, 1);
            v += __shfl_xor_sync(0xffffffffu, v, 2);
            if (lr == 0)
                atomicAdd(&rsum[mBase + mt * 16 + h * 8 + lq], v);
        }
    __syncthreads();
    if (tid < 128) {
        int gr = rowBase + tid;
        if (gr < count) {
            int n = sp.rowmap ? sp.rowmap[gr] : gr;
            atomicAdd(&sp.Ssum[n], rsum[tid]);
        }
    }
}

// ===========================================================================
// tf32 mma.sync GEMM. MODE 0: store C fp32 (+ optional fp8 x8 copy).
// MODE 1: sum-exp. BT=1: B [Nc,K]; BT=0: B [K,Nc].
// ===========================================================================
template <int MODE, int BT>
__global__ void __launch_bounds__(256, 2) mma_gemm(
    const float* __restrict__ A, int lda, const float* __restrict__ B,
    const float* __restrict__ bias, float* __restrict__ C,
    uint8_t* __restrict__ C8,
    float* __restrict__ Ssum, int M, int Nc, int K,
    const int* __restrict__ rowmap, const int* __restrict__ countPtr)
{
    __shared__ uint32_t As[128 * LDW];
    __shared__ uint32_t Bs[128 * LDW];
    __shared__ float rsum[128];

    const int count = countPtr ? *countPtr : M;
    const int rowBase = blockIdx.y * 128;
    if (rowBase >= count) return;
    const int colBase = blockIdx.x * 128;

    const int tid  = threadIdx.x;
    const int lane = tid & 31;
    const int wid  = tid >> 5;
    const int mBase = (wid & 1) * 64;
    const int nBase = (wid >> 1) * 32;
    const int lq = lane >> 2;
    const int lr = lane & 3;

    if (MODE == 1 && tid < 128) rsum[tid] = 0.f;

    const int ar  = tid >> 1;
    const int akk = (tid & 1) * 8;
    const int gA  = rowBase + ar;
    const bool aval = (gA < count);
    const int arow = aval ? (rowmap ? rowmap[gA] : gA) : 0;
    const float* Aptr = A + (size_t)arow * lda + akk;

    int br, bkk; bool bval; const float* Bptr;
    if (BT) {
        br  = tid >> 1;
        bkk = (tid & 1) * 8;
        bval = (colBase + br) < Nc;
        Bptr = B + (size_t)(bval ? colBase + br : 0) * K + bkk;
    } else {
        bkk = tid >> 4;
        br  = (tid & 15) * 8;
        bval = (colBase + br) < Nc;
        Bptr = B + colBase + (bval ? br : 0);
    }

    const float4 fz = make_float4(0.f, 0.f, 0.f, 0.f);
    float4 aR0, aR1, bR0, bR1;
    aR0 = aval ? *(const float4*)(Aptr)     : fz;
    aR1 = aval ? *(const float4*)(Aptr + 4) : fz;
    if (BT) {
        bR0 = bval ? *(const float4*)(Bptr)     : fz;
        bR1 = bval ? *(const float4*)(Bptr + 4) : fz;
    } else {
        bR0 = bval ? *(const float4*)(Bptr + (size_t)bkk * Nc)     : fz;
        bR1 = bval ? *(const float4*)(Bptr + (size_t)bkk * Nc + 4) : fz;
    }

    float acc[4][4][4];
#pragma unroll
    for (int i = 0; i < 4; i++)
#pragma unroll
        for (int j = 0; j < 4; j++)
#pragma unroll
            for (int r = 0; r < 4; r++) acc[i][j][r] = 0.f;

    for (int k0 = 0; k0 < K; k0 += 16) {
        {
            uint32_t* ap = &As[ar * LDW + akk];
            ap[0] = f2tf(aR0.x); ap[1] = f2tf(aR0.y); ap[2] = f2tf(aR0.z); ap[3] = f2tf(aR0.w);
            ap[4] = f2tf(aR1.x); ap[5] = f2tf(aR1.y); ap[6] = f2tf(aR1.z); ap[7] = f2tf(aR1.w);
            if (BT) {
                uint32_t* bp = &Bs[br * LDW + bkk];
                bp[0] = f2tf(bR0.x); bp[1] = f2tf(bR0.y); bp[2] = f2tf(bR0.z); bp[3] = f2tf(bR0.w);
                bp[4] = f2tf(bR1.x); bp[5] = f2tf(bR1.y); bp[6] = f2tf(bR1.z); bp[7] = f2tf(bR1.w);
            } else {
                float v[8] = {bR0.x, bR0.y, bR0.z, bR0.w, bR1.x, bR1.y, bR1.z, bR1.w};
#pragma unroll
                for (int q = 0; q < 8; q++) Bs[(br + q) * LDW + bkk] = f2tf(v[q]);
            }
        }
        __syncthreads();

        const int kn = k0 + 16;
        if (kn < K) {
            aR0 = aval ? *(const float4*)(Aptr + kn)     : fz;
            aR1 = aval ? *(const float4*)(Aptr + kn + 4) : fz;
            if (BT) {
                bR0 = bval ? *(const float4*)(Bptr + kn)     : fz;
                bR1 = bval ? *(const float4*)(Bptr + kn + 4) : fz;
            } else {
                bR0 = bval ? *(const float4*)(Bptr + (size_t)(kn + bkk) * Nc)     : fz;
                bR1 = bval ? *(const float4*)(Bptr + (size_t)(kn + bkk) * Nc + 4) : fz;
            }
        }

#pragma unroll
        for (int ks = 0; ks < 16; ks += 8) {
            uint32_t af[4][4], bf[4][2];
#pragma unroll
            for (int mt = 0; mt < 4; mt++) {
                int r = mBase + mt * 16 + lq;
                int c = ks + lr;
                af[mt][0] = As[r * LDW + c];
                af[mt][1] = As[(r + 8) * LDW + c];
                af[mt][2] = As[r * LDW + c + 4];
                af[mt][3] = As[(r + 8) * LDW + c + 4];
            }
#pragma unroll
            for (int nt = 0; nt < 4; nt++) {
                int n = nBase + nt * 8 + lq;
                bf[nt][0] = Bs[n * LDW + ks + lr];
                bf[nt][1] = Bs[n * LDW + ks + 4 + lr];
            }
#pragma unroll
            for (int mt = 0; mt < 4; mt++)
#pragma unroll
                for (int nt = 0; nt < 4; nt++)
                    MMA_TF32(acc[mt][nt], af[mt], bf[nt]);
        }
        __syncthreads();
    }

    if (MODE == 0) {
#pragma unroll
        for (int mt = 0; mt < 4; mt++) {
            int r0 = rowBase + mBase + mt * 16 + lq;
#pragma unroll
            for (int nt = 0; nt < 4; nt++) {
                int gc = colBase + nBase + nt * 8 + 2 * lr;
                if (gc < Nc) {
                    float* p0 = C + (size_t)r0 * Nc + gc;
                    float* p1 = C + (size_t)(r0 + 8) * Nc + gc;
                    p0[0] = acc[mt][nt][0]; p0[1] = acc[mt][nt][1];
                    p1[0] = acc[mt][nt][2]; p1[1] = acc[mt][nt][3];
                    if (C8) {
                        ((uint16_t*)C8)[((size_t)r0 * Nc + gc) >> 1] =
                            pack_e4m3(acc[mt][nt][0] * 8.f, acc[mt][nt][1] * 8.f);
                        ((uint16_t*)C8)[((size_t)(r0 + 8) * Nc + gc) >> 1] =
                            pack_e4m3(acc[mt][nt][2] * 8.f, acc[mt][nt][3] * 8.f);
                    }
                }
            }
        }
    } else {
        float rs[4][2];
#pragma unroll
        for (int mt = 0; mt < 4; mt++) { rs[mt][0] = 0.f; rs[mt][1] = 0.f; }
#pragma unroll
        for (int nt = 0; nt < 4; nt++) {
            int gc = colBase + nBase + nt * 8 + 2 * lr;
            bool v0 = gc < Nc, v1 = (gc + 1) < Nc;
            float bv0 = v0 ? bias[gc] : 0.f;
            float bv1 = v1 ? bias[gc + 1] : 0.f;
#pragma unroll
            for (int mt = 0; mt < 4; mt++) {
                if (v0) {
                    rs[mt][0] += __expf(acc[mt][nt][0] + bv0);
                    rs[mt][1] += __expf(acc[mt][nt][2] + bv0);
                }
                if (v1) {
                    rs[mt][0] += __expf(acc[mt][nt][1] + bv1);
                    rs[mt][1] += __expf(acc[mt][nt][3] + bv1);
                }
            }
        }
#pragma unroll
        for (int mt = 0; mt < 4; mt++)
#pragma unroll
            for (int h = 0; h < 2; h++) {
                float v = rs[mt][h];
                v += __shfl_xor_sync(0xffffffffu, v, 1);
                v += __shfl_xor_sync(0xffffffffu, v, 2);
                if (lr == 0)
                    atomicAdd(&rsum[mBase + mt * 16 + h * 8 + lq], v);
            }
        __syncthreads();
        if (tid < 128) {
            int gr = rowBase + tid;
            if (gr < count) {
                int n = rowmap ? rowmap[gr] : gr;
                atomicAdd(&Ssum[n], rsum[tid]);
            }
        }
    }
}

// ---------------- prep / bufprep / gather / combine -------------------------
__global__ void prep_kernel(const int* __restrict__ target) {
    int i = threadIdx.x;
    g_S0[i] = 0.f; g_St[i] = 0.f;
    if (i < 3) g_count[i] = 0;
    __syncthreads();
    int t = target[i];
    int c = (t < 20000) ? 0 : (t < 40000) ? 1 : (t < 200000) ? 2 : 3;
    g_cluster[i] = c;
    if (c > 0) {
        int idx = atomicAdd(&g_count[c - 1], 1);
        g_rowlist[(c - 1) * NROWS + idx] = i;
    }
}

__global__ void bufprep_kernel(
    const float4* __restrict__ p0, const float4* __restrict__ p1,
    const float4* __restrict__ p2, const float4* __restrict__ p3,
    const float4* __restrict__ w0, const float4* __restrict__ w1,
    const float4* __restrict__ w2)
{
    const int T0 = 348160;
    const int T1 = T0 + 5120768;
    const int T2 = T1 + 1280000;
    const int T3 = T2 + 2560000;
    for (int i = blockIdx.x * blockDim.x + threadIdx.x; i < T3;
         i += gridDim.x * blockDim.x) {
        if (i < T0) {
            int k = i / 340, c4 = i - k * 340;
            float4 v;
            if (c4 < 256)      v = p0[k * 256 + c4];
            else if (c4 < 320) v = p1[k * 64 + (c4 - 256)];
            else if (c4 < 336) v = p2[k * 16 + (c4 - 320)];
            else               v = p3[k * 4 + (c4 - 336)];
            ((float4*)g_wcat)[i] = v;
        } else if (i < T1) {
            int j = i - T0;
            ((uint32_t*)g_w0b)[j] = pack4_e4m3_x8(w0[j]);
        } else if (i < T2) {
            int j = i - T1;
            ((uint32_t*)g_w1b)[j] = pack4_e4m3_x8(w1[j]);
        } else {
            int j = i - T2;
            ((uint32_t*)g_w2b)[j] = pack4_e4m3_x8(w2[j]);
        }
    }
}

__global__ void gather_kernel(
    const float* __restrict__ w0, const float* __restrict__ b0,
    const float* __restrict__ w1, const float* __restrict__ b1,
    const float* __restrict__ w2, const float* __restrict__ b2,
    const float* __restrict__ w3, const float* __restrict__ b3,
    const int* __restrict__ target)
{
    int gw = (blockIdx.x * blockDim.x + threadIdx.x) >> 5;
    int lane = threadIdx.x & 31;
    if (gw < NROWS) {
        int c = g_cluster[gw];
        int col = (c == 0) ? target[gw] : (HEAD_SIZE - c);
        const float4* pr = (const float4*)(g_proj + (size_t)gw * PCW);
        const float4* wr = (const float4*)(w0 + (size_t)col * 1024);
        float s = 0.f;
        for (int i = lane; i < 256; i += 32) {
            float4 a = pr[i], b = wr[i];
            s += a.x * b.x + a.y * b.y + a.z * b.z + a.w * b.w;
        }
#pragma unroll
        for (int o = 16; o; o >>= 1) s += __shfl_down_sync(0xffffffffu, s, o);
        if (lane == 0) g_ghead[gw] = s + b0[col];
    } else if (gw < 2 * NROWS) {
        int w = gw - NROWS;
        int c = g_cluster[w];
        if (c == 0) return;
        const float* pr; const float* W; const float* bb; int K, off;
        if (c == 1)      { pr = g_proj + (size_t)w * PCW + 1024; W = w1; bb = b1; K = 256; off = 20000; }
        else if (c == 2) { pr = g_proj + (size_t)w * PCW + 1280; W = w2; bb = b2; K = 64;  off = 40000; }
        else             { pr = g_proj + (size_t)w * PCW + 1344; W = w3; bb = b3; K = 16;  off = 200000; }
        int ti = target[w] - off;
        float s = 0.f;
        for (int k = lane; k < K; k += 32) s += pr[k] * W[(size_t)ti * K + k];
#pragma unroll
        for (int o = 16; o; o >>= 1) s += __shfl_down_sync(0xffffffffu, s, o);
        if (lane == 0) g_gtail[w] = s + bb[ti];
    }
}

__global__ void combine_kernel(float* __restrict__ out, int n) {
    int i = blockIdx.x * blockDim.x + threadIdx.x;
    if (i >= n) return;
    float v = logf(g_S0[i]) - g_ghead[i];
    if (g_cluster[i] > 0) v += logf(g_St[i]) - g_gtail[i];
    out[i] = v;
}

// ---------------- launch ----------------------------------------------------
extern "C" void kernel_launch(void* const* d_in, const int* in_sizes, int n_in,
                              void* d_out, int out_size) {
    const float* hidden = (const float*)d_in[0];
    const int*   target = (const int*)d_in[1];
    const float* w0 = (const float*)d_in[2];
    const float* b0 = (const float*)d_in[3];
    const float* p0 = (const float*)d_in[4];
    const float* w1 = (const float*)d_in[5];
    const float* b1 = (const float*)d_in[6];
    const float* p1 = (const float*)d_in[7];
    const float* w2 = (const float*)d_in[8];
    const float* b2 = (const float*)d_in[9];
    const float* p2 = (const float*)d_in[10];
    const float* w3 = (const float*)d_in[11];
    const float* b3 = (const float*)d_in[12];
    const float* p3 = (const float*)d_in[13];
    float* out = (float*)d_out;

    float *wcat, *proj, *S0, *St;
    uint8_t *proj8, *w0b, *w1b, *w2b;
    int *rowlist, *cnt;
    cudaGetSymbolAddress((void**)&wcat, g_wcat);
    cudaGetSymbolAddress((void**)&proj, g_proj);
    cudaGetSymbolAddress((void**)&proj8, g_proj8);
    cudaGetSymbolAddress((void**)&w0b, g_w0b);
    cudaGetSymbolAddress((void**)&w1b, g_w1b);
    cudaGetSymbolAddress((void**)&w2b, g_w2b);
    cudaGetSymbolAddress((void**)&S0, g_S0);
    cudaGetSymbolAddress((void**)&St, g_St);
    cudaGetSymbolAddress((void**)&rowlist, g_rowlist);
    cudaGetSymbolAddress((void**)&cnt, g_count);

    const int N = NROWS;

    prep_kernel<<<1, 1024>>>(target);
    bufprep_kernel<<<2048, 256>>>((const float4*)p0, (const float4*)p1,
                                  (const float4*)p2, (const float4*)p3,
                                  (const float4*)w0, (const float4*)w1,
                                  (const float4*)w2);

    // proj_cat = hidden @ wcat  (tf32 NN, fp32 + fp8 outputs)
    mma_gemm<0, 0><<<dim3(11, 8, 1), 256>>>(
        hidden, 1024, wcat, nullptr, proj, proj8, nullptr,
        N, PCW, 1024, nullptr, nullptr);

    // merged fp8 sum-exp: head (first: longest K), tail2, tail1
    SEP3 P;
    // head: Nc=20003, K=1024, nx=157, 1256 CTAs
    P.p[0] = { proj8,        w0b, b0, S0, HEAD_SIZE, 1024, 157, 0,
               nullptr, nullptr };
    // tail2: Nc=160000, K=64, nx=1250, 10000 CTAs
    P.p[1] = { proj8 + 1280, w2b, b2, St, 160000, 64, 1250, 1256,
               rowlist + 1 * NROWS, cnt + 1 };
    // tail1: Nc=20000, K=256, nx=157, 1256 CTAs
    P.p[2] = { proj8 + 1024, w1b, b1, St, 20000, 256, 157, 11256,
               rowlist + 0 * NROWS, cnt + 0 };
    fp8_sumexp_multi<<<12512, 256>>>(P);

    // tail3 (K=16, tf32)
    mma_gemm<1, 1><<<dim3(530, 8, 1), 256>>>(
        proj + 1344, PCW, w3, b3, nullptr, nullptr, St,
        N, 67735, 16, rowlist + 2 * NROWS, cnt + 2);

    gather_kernel<<<256, 256>>>(w0, b0, w1, b1, w2, b2, w3, b3, target);
    combine_kernel<<<(N + 255) / 256, 256>>>(out, N);
}

// round 10
// speedup vs baseline: 4.4290x; 1.0089x over previous
#include <cuda_runtime.h>
#include <cuda_bf16.h>
#include <math.h>
#include <stdint.h>

// ---------------------------------------------------------------------------
// AdaptiveLogSoftmax NLL.
//   prep:    init + classify rows into clusters
//   bufprep: concat proj weights -> wcat; convert w0/w1/w2/w3 -> e4m3 (x8),
//            w3 zero-padded K16->K64; zero proj8 row padding (stride 1408)
//   proj:    proj_cat = hidden @ wcat (tf32 mma.sync), fp32 + fp8(x8) outputs
//   ONE fp8 launch: head + tail1 + tail2 + tail3 sum-exp GEMMs
//            (m16n8k32 e4m3, cp.async staging, exp2 epilogue, x64 descale)
//   gather:  exact fp32 dot for target logits;  combine: final NLL
// ---------------------------------------------------------------------------

#define NROWS 1024
#define HEAD_SIZE 20003
#define PCW 1360          // fp32 proj row width
#define PCWP 1408         // fp8 proj row stride (48B zero pad for tail3 chunk)
#define LOG2E 1.4426950408889634f
#define INV64_LOG2E (LOG2E / 64.f)

__device__ __align__(16) float    g_wcat[1024 * PCW];
__device__ __align__(16) float    g_proj[NROWS * PCW];
__device__ __align__(16) uint8_t  g_proj8[NROWS * PCWP];
__device__ __align__(16) uint8_t  g_w0b[20003 * 1024];
__device__ __align__(16) uint8_t  g_w1b[20000 * 256];
__device__ __align__(16) uint8_t  g_w2b[160000 * 64];
__device__ __align__(16) uint8_t  g_w3b[67735 * 64];   // 16 data + 48 zero
__device__ float g_S0[NROWS];
__device__ float g_St[NROWS];
__device__ float g_ghead[NROWS];
__device__ float g_gtail[NROWS];
__device__ int   g_rowlist[3 * NROWS];
__device__ int   g_count[3];
__device__ int   g_cluster[NROWS];

// ---------------- helpers ---------------------------------------------------
__device__ __forceinline__ uint32_t f2tf(float f) {
    uint32_t r;
    asm("cvt.rna.tf32.f32 %0, %1;" : "=r"(r) : "f"(f));
    return r;
}
__device__ __forceinline__ uint16_t pack_e4m3(float lo, float hi) {
    uint16_t r;
    asm("cvt.rn.satfinite.e4m3x2.f32 %0, %1, %2;" : "=h"(r) : "f"(hi), "f"(lo));
    return r;
}
__device__ __forceinline__ uint32_t pack4_e4m3_x8(float4 v) {
    uint16_t l = pack_e4m3(v.x * 8.f, v.y * 8.f);
    uint16_t h = pack_e4m3(v.z * 8.f, v.w * 8.f);
    return (uint32_t)l | ((uint32_t)h << 16);
}

#define MMA_TF32(c, a, b)                                                     \
    asm volatile(                                                             \
        "mma.sync.aligned.m16n8k8.row.col.f32.tf32.tf32.f32 "                 \
        "{%0,%1,%2,%3},{%4,%5,%6,%7},{%8,%9},{%0,%1,%2,%3};"                  \
        : "+f"(c[0]), "+f"(c[1]), "+f"(c[2]), "+f"(c[3])                      \
        : "r"(a[0]), "r"(a[1]), "r"(a[2]), "r"(a[3]), "r"(b[0]), "r"(b[1]))

#define MMA_FP8(c, a0, a1, a2, a3, b0, b1)                                    \
    asm volatile(                                                             \
        "mma.sync.aligned.m16n8k32.row.col.f32.e4m3.e4m3.f32 "                \
        "{%0,%1,%2,%3},{%4,%5,%6,%7},{%8,%9},{%0,%1,%2,%3};"                  \
        : "+f"(c[0]), "+f"(c[1]), "+f"(c[2]), "+f"(c[3])                      \
        : "r"(a0), "r"(a1), "r"(a2), "r"(a3), "r"(b0), "r"(b1))

#define LDSM4(r0, r1, r2, r3, addr)                                           \
    asm volatile("ldmatrix.sync.aligned.m8n8.x4.shared.b16 {%0,%1,%2,%3}, [%4];" \
        : "=r"(r0), "=r"(r1), "=r"(r2), "=r"(r3) : "r"(addr))

#define CP_ASYNC16(smem, gptr)                                                \
    asm volatile("cp.async.cg.shared.global [%0], [%1], 16;"                  \
        :: "r"(smem), "l"(gptr) : "memory")
#define CP_COMMIT() asm volatile("cp.async.commit_group;" ::: "memory")
#define CP_WAIT0()  asm volatile("cp.async.wait_group 0;" ::: "memory")

#define LDW 20                 // words per row: 16 data (64B) + 4 pad
#define BUFB (128 * LDW * 4)   // bytes per buffer per matrix

// ---------------- merged fp8 sum-exp problem table --------------------------
struct SEP {
    const uint8_t* A;
    const uint8_t* B;
    const float*   bias;
    float*         Ssum;
    int Nc, K, nx, base;
    const int* rowmap;
    const int* countPtr;
};
struct SEP4 { SEP p[4]; };

// ===========================================================================
// fp8 GEMM + fused sum-exp, cp.async double-buffered. Tile 128x128, K64
// chunks. 256 threads, 8 warps (2Mx4N). Operands x8 each -> acc = 64x logit.
// ===========================================================================
__global__ void __launch_bounds__(256, 2) fp8_sumexp_multi(SEP4 P)
{
    __shared__ __align__(16) uint32_t As[2][128 * LDW];
    __shared__ __align__(16) uint32_t Bs[2][128 * LDW];
    __shared__ float rsum[128];

    const int bx = blockIdx.x;
    const int pi = (bx >= P.p[1].base) + (bx >= P.p[2].base) + (bx >= P.p[3].base);
    const SEP sp = P.p[pi];
    const int local = bx - sp.base;
    const int tileX = local % sp.nx;
    const int tileY = local / sp.nx;

    const int count = sp.countPtr ? *sp.countPtr : NROWS;
    const int rowBase = tileY * 128;
    if (rowBase >= count) return;
    const int colBase = tileX * 128;
    const int Nc = sp.Nc, K = sp.K;

    const int tid  = threadIdx.x;
    const int lane = tid & 31;
    const int wid  = tid >> 5;
    const int mBase = (wid & 1) * 64;
    const int nBase = (wid >> 1) * 32;
    const int lq = lane >> 2;
    const int lr = lane & 3;

    if (tid < 128) rsum[tid] = 0.f;

    // loaders: row = tid/2, half = 32 bytes of the 64B k-chunk
    const int ar   = tid >> 1;
    const int half = tid & 1;
    const int gA   = rowBase + ar;
    const bool aval = (gA < count);
    const int arow = aval ? (sp.rowmap ? sp.rowmap[gA] : gA) : 0;
    const uint8_t* Ag = sp.A + (size_t)arow * PCWP + half * 32;
    int gB = colBase + ar; if (gB >= Nc) gB = Nc - 1;
    const uint8_t* Bg = sp.B + (size_t)gB * K + half * 32;

    const uint32_t asb = (uint32_t)__cvta_generic_to_shared(&As[0][0]);
    const uint32_t bsb = (uint32_t)__cvta_generic_to_shared(&Bs[0][0]);
    const uint32_t aSlot = asb + (ar * LDW + half * 8) * 4;
    const uint32_t bSlot = bsb + (ar * LDW + half * 8) * 4;
    const uint32_t aBase0 = asb + ((mBase + (lane & 15)) * LDW + (lane >> 4) * 4) * 4;
    const uint32_t bBase0 = bsb + ((nBase + lane) * LDW) * 4;

    float acc[4][4][4];
#pragma unroll
    for (int i = 0; i < 4; i++)
#pragma unroll
        for (int j = 0; j < 4; j++)
#pragma unroll
            for (int r = 0; r < 4; r++) acc[i][j][r] = 0.f;

    // chunk 0 -> buffer 0
    CP_ASYNC16(aSlot, Ag);      CP_ASYNC16(aSlot + 16, Ag + 16);
    CP_ASYNC16(bSlot, Bg);      CP_ASYNC16(bSlot + 16, Bg + 16);
    CP_COMMIT();

    const int nch = K >> 6;
    uint32_t buf = 0;
    CP_WAIT0();
    __syncthreads();

    for (int c = 0; c < nch; ++c) {
        const bool more = (c + 1 < nch);
        if (more) {
            // prefetch next chunk into the other buffer (safe: its consumers
            // finished before the previous iteration's trailing sync)
            const uint32_t nb = (buf ^ 1) * BUFB;
            const uint8_t* an = Ag + ((c + 1) << 6);
            const uint8_t* bn = Bg + ((c + 1) << 6);
            CP_ASYNC16(aSlot + nb, an); CP_ASYNC16(aSlot + nb + 16, an + 16);
            CP_ASYNC16(bSlot + nb, bn); CP_ASYNC16(bSlot + nb + 16, bn + 16);
            CP_COMMIT();
        }

        const uint32_t aB = aBase0 + buf * BUFB;
        const uint32_t bB = bBase0 + buf * BUFB;
#pragma unroll
        for (int cc = 0; cc < 2; ++cc) {
            uint32_t af[4][4], b0r[4], b1r[4];
            LDSM4(b0r[0], b0r[1], b0r[2], b0r[3], bB + cc * 32);
            LDSM4(b1r[0], b1r[1], b1r[2], b1r[3], bB + cc * 32 + 16);
#pragma unroll
            for (int mt = 0; mt < 4; mt++)
                LDSM4(af[mt][0], af[mt][1], af[mt][2], af[mt][3],
                      aB + mt * (16 * LDW * 4) + cc * 32);
#pragma unroll
            for (int mt = 0; mt < 4; mt++)
#pragma unroll
                for (int nt = 0; nt < 4; nt++)
                    MMA_FP8(acc[mt][nt],
                            af[mt][0], af[mt][1], af[mt][2], af[mt][3],
                            b0r[nt], b1r[nt]);
        }

        if (more) {
            CP_WAIT0();
            __syncthreads();
            buf ^= 1;
        }
    }

    // fused sum-exp epilogue (exp2, folded scales)
    float rs[4][2];
#pragma unroll
    for (int mt = 0; mt < 4; mt++) { rs[mt][0] = 0.f; rs[mt][1] = 0.f; }

    const float* bptr = sp.bias + colBase + nBase;
    if (colBase + 128 <= Nc) {
        // interior tile: no bounds predicates
#pragma unroll
        for (int nt = 0; nt < 4; nt++) {
            int cc0 = nt * 8 + 2 * lr;
            float bv0 = bptr[cc0] * LOG2E;
            float bv1 = bptr[cc0 + 1] * LOG2E;
#pragma unroll
            for (int mt = 0; mt < 4; mt++) {
                rs[mt][0] += exp2f(fmaf(acc[mt][nt][0], INV64_LOG2E, bv0));
                rs[mt][1] += exp2f(fmaf(acc[mt][nt][2], INV64_LOG2E, bv0));
                rs[mt][0] += exp2f(fmaf(acc[mt][nt][1], INV64_LOG2E, bv1));
                rs[mt][1] += exp2f(fmaf(acc[mt][nt][3], INV64_LOG2E, bv1));
            }
        }
    } else {
#pragma unroll
        for (int nt = 0; nt < 4; nt++) {
            int gc = colBase + nBase + nt * 8 + 2 * lr;
            bool v0 = gc < Nc, v1 = (gc + 1) < Nc;
            float bv0 = v0 ? sp.bias[gc] * LOG2E : 0.f;
            float bv1 = v1 ? sp.bias[gc + 1] * LOG2E : 0.f;
#pragma unroll
            for (int mt = 0; mt < 4; mt++) {
                if (v0) {
                    rs[mt][0] += exp2f(fmaf(acc[mt][nt][0], INV64_LOG2E, bv0));
                    rs[mt][1] += exp2f(fmaf(acc[mt][nt][2], INV64_LOG2E, bv0));
                }
                if (v1) {
                    rs[mt][0] += exp2f(fmaf(acc[mt][nt][1], INV64_LOG2E, bv1));
                    rs[mt][1] += exp2f(fmaf(acc[mt][nt][3], INV64_LOG2E, bv1));
                }
            }
        }
    }
#pragma unroll
    for (int mt = 0; mt < 4; mt++)
#pragma unroll
        for (int h = 0; h < 2; h++) {
            float v = rs[mt][h];
            v += __shfl_xor_sync(0xffffffffu, v, 1);
            v += __shfl_xor_sync(0xffffffffu, v, 2);
            if (lr == 0)
                atomicAdd(&rsum[mBase + mt * 16 + h * 8 + lq], v);
        }
    __syncthreads();
    if (tid < 128) {
        int gr = rowBase + tid;
        if (gr < count) {
            int n = sp.rowmap ? sp.rowmap[gr] : gr;
            atomicAdd(&sp.Ssum[n], rsum[tid]);
        }
    }
}

// ===========================================================================
// tf32 mma.sync GEMM (proj store path). C fp32 [M,Nc] + fp8 x8 copy at
// row stride PCWP. B [K,Nc] row-major (NN).
// ===========================================================================
__global__ void __launch_bounds__(256, 2) proj_gemm(
    const float* __restrict__ A, const float* __restrict__ B,
    float* __restrict__ C, uint8_t* __restrict__ C8, int Nc, int K)
{
    __shared__ uint32_t As[128 * LDW];
    __shared__ uint32_t Bs[128 * LDW];

    const int rowBase = blockIdx.y * 128;
    const int colBase = blockIdx.x * 128;

    const int tid  = threadIdx.x;
    const int lane = tid & 31;
    const int wid  = tid >> 5;
    const int mBase = (wid & 1) * 64;
    const int nBase = (wid >> 1) * 32;
    const int lq = lane >> 2;
    const int lr = lane & 3;

    const int ar  = tid >> 1;
    const int akk = (tid & 1) * 8;
    const float* Aptr = A + (size_t)(rowBase + ar) * K + akk;

    const int bkk = tid >> 4;
    const int br  = (tid & 15) * 8;
    const bool bval = (colBase + br) < Nc;
    const float* Bptr = B + colBase + (bval ? br : 0);

    const float4 fz = make_float4(0.f, 0.f, 0.f, 0.f);
    float4 aR0, aR1, bR0, bR1;
    aR0 = *(const float4*)(Aptr);
    aR1 = *(const float4*)(Aptr + 4);
    bR0 = bval ? *(const float4*)(Bptr + (size_t)bkk * Nc)     : fz;
    bR1 = bval ? *(const float4*)(Bptr + (size_t)bkk * Nc + 4) : fz;

    float acc[4][4][4];
#pragma unroll
    for (int i = 0; i < 4; i++)
#pragma unroll
        for (int j = 0; j < 4; j++)
#pragma unroll
            for (int r = 0; r < 4; r++) acc[i][j][r] = 0.f;

    for (int k0 = 0; k0 < K; k0 += 16) {
        {
            uint32_t* ap = &As[ar * LDW + akk];
            ap[0] = f2tf(aR0.x); ap[1] = f2tf(aR0.y); ap[2] = f2tf(aR0.z); ap[3] = f2tf(aR0.w);
            ap[4] = f2tf(aR1.x); ap[5] = f2tf(aR1.y); ap[6] = f2tf(aR1.z); ap[7] = f2tf(aR1.w);
            float v[8] = {bR0.x, bR0.y, bR0.z, bR0.w, bR1.x, bR1.y, bR1.z, bR1.w};
#pragma unroll
            for (int q = 0; q < 8; q++) Bs[(br + q) * LDW + bkk] = f2tf(v[q]);
        }
        __syncthreads();

        const int kn = k0 + 16;
        if (kn < K) {
            aR0 = *(const float4*)(Aptr + kn);
            aR1 = *(const float4*)(Aptr + kn + 4);
            bR0 = bval ? *(const float4*)(Bptr + (size_t)(kn + bkk) * Nc)     : fz;
            bR1 = bval ? *(const float4*)(Bptr + (size_t)(kn + bkk) * Nc + 4) : fz;
        }

#pragma unroll
        for (int ks = 0; ks < 16; ks += 8) {
            uint32_t af[4][4], bf[4][2];
#pragma unroll
            for (int mt = 0; mt < 4; mt++) {
                int r = mBase + mt * 16 + lq;
                int c = ks + lr;
                af[mt][0] = As[r * LDW + c];
                af[mt][1] = As[(r + 8) * LDW + c];
                af[mt][2] = As[r * LDW + c + 4];
                af[mt][3] = As[(r + 8) * LDW + c + 4];
            }
#pragma unroll
            for (int nt = 0; nt < 4; nt++) {
                int n = nBase + nt * 8 + lq;
                bf[nt][0] = Bs[n * LDW + ks + lr];
                bf[nt][1] = Bs[n * LDW + ks + 4 + lr];
            }
#pragma unroll
            for (int mt = 0; mt < 4; mt++)
#pragma unroll
                for (int nt = 0; nt < 4; nt++)
                    MMA_TF32(acc[mt][nt], af[mt], bf[nt]);
        }
        __syncthreads();
    }

#pragma unroll
    for (int mt = 0; mt < 4; mt++) {
        int r0 = rowBase + mBase + mt * 16 + lq;
#pragma unroll
        for (int nt = 0; nt < 4; nt++) {
            int gc = colBase + nBase + nt * 8 + 2 * lr;
            if (gc < Nc) {
                float* p0 = C + (size_t)r0 * Nc + gc;
                float* p1 = C + (size_t)(r0 + 8) * Nc + gc;
                p0[0] = acc[mt][nt][0]; p0[1] = acc[mt][nt][1];
                p1[0] = acc[mt][nt][2]; p1[1] = acc[mt][nt][3];
                ((uint16_t*)C8)[((size_t)r0 * PCWP + gc) >> 1] =
                    pack_e4m3(acc[mt][nt][0] * 8.f, acc[mt][nt][1] * 8.f);
                ((uint16_t*)C8)[((size_t)(r0 + 8) * PCWP + gc) >> 1] =
                    pack_e4m3(acc[mt][nt][2] * 8.f, acc[mt][nt][3] * 8.f);
            }
        }
    }
}

// ---------------- prep / bufprep / gather / combine -------------------------
__global__ void prep_kernel(const int* __restrict__ target) {
    int i = threadIdx.x;
    g_S0[i] = 0.f; g_St[i] = 0.f;
    if (i < 3) g_count[i] = 0;
    __syncthreads();
    int t = target[i];
    int c = (t < 20000) ? 0 : (t < 40000) ? 1 : (t < 200000) ? 2 : 3;
    g_cluster[i] = c;
    if (c > 0) {
        int idx = atomicAdd(&g_count[c - 1], 1);
        g_rowlist[(c - 1) * NROWS + idx] = i;
    }
}

__global__ void bufprep_kernel(
    const float4* __restrict__ p0, const float4* __restrict__ p1,
    const float4* __restrict__ p2, const float4* __restrict__ p3,
    const float4* __restrict__ w0, const float4* __restrict__ w1,
    const float4* __restrict__ w2, const float4* __restrict__ w3)
{
    const int T0 = 348160;            // wcat: 1024*1360/4
    const int T1 = T0 + 5120768;      // w0:   20003*1024/4
    const int T2 = T1 + 1280000;      // w1:   20000*256/4
    const int T3 = T2 + 2560000;      // w2:   160000*64/4
    const int T4 = T3 + 270940;       // w3:   67735*16/4 (data)
    const int T5 = T4 + 812820;       // w3 pad zeros: 67735*12
    const int T6 = T5 + 12288;        // proj8 pad zeros: 1024*12
    for (int i = blockIdx.x * blockDim.x + threadIdx.x; i < T6;
         i += gridDim.x * blockDim.x) {
        if (i < T0) {
            int k = i / 340, c4 = i - k * 340;
            float4 v;
            if (c4 < 256)      v = p0[k * 256 + c4];
            else if (c4 < 320) v = p1[k * 64 + (c4 - 256)];
            else if (c4 < 336) v = p2[k * 16 + (c4 - 320)];
            else               v = p3[k * 4 + (c4 - 336)];
            ((float4*)g_wcat)[i] = v;
        } else if (i < T1) {
            int j = i - T0;
            ((uint32_t*)g_w0b)[j] = pack4_e4m3_x8(w0[j]);
        } else if (i < T2) {
            int j = i - T1;
            ((uint32_t*)g_w1b)[j] = pack4_e4m3_x8(w1[j]);
        } else if (i < T3) {
            int j = i - T2;
            ((uint32_t*)g_w2b)[j] = pack4_e4m3_x8(w2[j]);
        } else if (i < T4) {
            int j = i - T3;                    // float4 group of w3
            int row = j >> 2, q = j & 3;
            ((uint32_t*)g_w3b)[row * 16 + q] = pack4_e4m3_x8(w3[j]);
        } else if (i < T5) {
            int j = i - T4;                    // zero pad of w3b
            int row = j / 12, word = j - row * 12;
            ((uint32_t*)g_w3b)[row * 16 + 4 + word] = 0u;
        } else {
            int j = i - T5;                    // zero pad of proj8
            int row = j / 12, word = j - row * 12;
            ((uint32_t*)g_proj8)[row * 352 + 340 + word] = 0u;
        }
    }
}

__global__ void gather_kernel(
    const float* __restrict__ w0, const float* __restrict__ b0,
    const float* __restrict__ w1, const float* __restrict__ b1,
    const float* __restrict__ w2, const float* __restrict__ b2,
    const float* __restrict__ w3, const float* __restrict__ b3,
    const int* __restrict__ target)
{
    int gw = (blockIdx.x * blockDim.x + threadIdx.x) >> 5;
    int lane = threadIdx.x & 31;
    if (gw < NROWS) {
        int c = g_cluster[gw];
        int col = (c == 0) ? target[gw] : (HEAD_SIZE - c);
        const float4* pr = (const float4*)(g_proj + (size_t)gw * PCW);
        const float4* wr = (const float4*)(w0 + (size_t)col * 1024);
        float s = 0.f;
        for (int i = lane; i < 256; i += 32) {
            float4 a = pr[i], b = wr[i];
            s += a.x * b.x + a.y * b.y + a.z * b.z + a.w * b.w;
        }
#pragma unroll
        for (int o = 16; o; o >>= 1) s += __shfl_down_sync(0xffffffffu, s, o);
        if (lane == 0) g_ghead[gw] = s + b0[col];
    } else if (gw < 2 * NROWS) {
        int w = gw - NROWS;
        int c = g_cluster[w];
        if (c == 0) return;
        const float* pr; const float* W; const float* bb; int K, off;
        if (c == 1)      { pr = g_proj + (size_t)w * PCW + 1024; W = w1; bb = b1; K = 256; off = 20000; }
        else if (c == 2) { pr = g_proj + (size_t)w * PCW + 1280; W = w2; bb = b2; K = 64;  off = 40000; }
        else             { pr = g_proj + (size_t)w * PCW + 1344; W = w3; bb = b3; K = 16;  off = 200000; }
        int ti = target[w] - off;
        float s = 0.f;
        for (int k = lane; k < K; k += 32) s += pr[k] * W[(size_t)ti * K + k];
#pragma unroll
        for (int o = 16; o; o >>= 1) s += __shfl_down_sync(0xffffffffu, s, o);
        if (lane == 0) g_gtail[w] = s + bb[ti];
    }
}

__global__ void combine_kernel(float* __restrict__ out, int n) {
    int i = blockIdx.x * blockDim.x + threadIdx.x;
    if (i >= n) return;
    float v = logf(g_S0[i]) - g_ghead[i];
    if (g_cluster[i] > 0) v += logf(g_St[i]) - g_gtail[i];
    out[i] = v;
}

// ---------------- launch ----------------------------------------------------
extern "C" void kernel_launch(void* const* d_in, const int* in_sizes, int n_in,
                              void* d_out, int out_size) {
    const float* hidden = (const float*)d_in[0];
    const int*   target = (const int*)d_in[1];
    const float* w0 = (const float*)d_in[2];
    const float* b0 = (const float*)d_in[3];
    const float* p0 = (const float*)d_in[4];
    const float* w1 = (const float*)d_in[5];
    const float* b1 = (const float*)d_in[6];
    const float* p1 = (const float*)d_in[7];
    const float* w2 = (const float*)d_in[8];
    const float* b2 = (const float*)d_in[9];
    const float* p2 = (const float*)d_in[10];
    const float* w3 = (const float*)d_in[11];
    const float* b3 = (const float*)d_in[12];
    const float* p3 = (const float*)d_in[13];
    float* out = (float*)d_out;

    float *wcat, *proj, *S0, *St;
    uint8_t *proj8, *w0b, *w1b, *w2b, *w3b;
    int *rowlist, *cnt;
    cudaGetSymbolAddress((void**)&wcat, g_wcat);
    cudaGetSymbolAddress((void**)&proj, g_proj);
    cudaGetSymbolAddress((void**)&proj8, g_proj8);
    cudaGetSymbolAddress((void**)&w0b, g_w0b);
    cudaGetSymbolAddress((void**)&w1b, g_w1b);
    cudaGetSymbolAddress((void**)&w2b, g_w2b);
    cudaGetSymbolAddress((void**)&w3b, g_w3b);
    cudaGetSymbolAddress((void**)&S0, g_S0);
    cudaGetSymbolAddress((void**)&St, g_St);
    cudaGetSymbolAddress((void**)&rowlist, g_rowlist);
    cudaGetSymbolAddress((void**)&cnt, g_count);

    const int N = NROWS;

    prep_kernel<<<1, 1024>>>(target);
    bufprep_kernel<<<2048, 256>>>((const float4*)p0, (const float4*)p1,
                                  (const float4*)p2, (const float4*)p3,
                                  (const float4*)w0, (const float4*)w1,
                                  (const float4*)w2, (const float4*)w3);

    // proj_cat = hidden @ wcat  (tf32 NN, fp32 + fp8 outputs)
    proj_gemm<<<dim3(11, 8, 1), 256>>>(hidden, wcat, proj, proj8, PCW, 1024);

    // ONE merged fp8 sum-exp launch: head, tail1, tail3, tail2
    SEP4 P;
    P.p[0] = { proj8,        w0b, b0, S0, HEAD_SIZE, 1024, 157, 0,
               nullptr, nullptr };                                   // 1256
    P.p[1] = { proj8 + 1024, w1b, b1, St, 20000, 256, 157, 1256,
               rowlist + 0 * NROWS, cnt + 0 };                       // 1256
    P.p[2] = { proj8 + 1344, w3b, b3, St, 67735, 64, 530, 2512,
               rowlist + 2 * NROWS, cnt + 2 };                       // 4240
    P.p[3] = { proj8 + 1280, w2b, b2, St, 160000, 64, 1250, 6752,
               rowlist + 1 * NROWS, cnt + 1 };                       // 10000
    fp8_sumexp_multi<<<16752, 256>>>(P);

    gather_kernel<<<256, 256>>>(w0, b0, w1, b1, w2, b2, w3, b3, target);
    combine_kernel<<<(N + 255) / 256, 256>>>(out, N);
}

// round 11
// speedup vs baseline: 4.4962x; 1.0152x over previous
#include <cuda_runtime.h>
#include <cuda_bf16.h>
#include <math.h>
#include <stdint.h>

// ---------------------------------------------------------------------------
// AdaptiveLogSoftmax NLL.
//   prep:    init + classify rows into clusters
//   bufprep: concat proj weights -> wcat; convert w0..w3 -> e4m3 (x8),
//            w3 zero-padded K16->K64; zero proj8 row padding (stride 1408)
//   proj:    proj_cat = hidden @ wcat (tf32 mma.sync), fp32 + fp8(x8) outputs
//   ONE fp8 launch: head + tail1 + tail3 + tail2 sum-exp GEMMs
//            (m16n8k32 e4m3, 3-stage cp.async pipeline, exp2 epilogue)
//   gather:  exact fp32 dot for target logits;  combine: final NLL
// ---------------------------------------------------------------------------

#define NROWS 1024
#define HEAD_SIZE 20003
#define PCW 1360
#define PCWP 1408
#define LOG2E 1.4426950408889634f
#define INV64_LOG2E (LOG2E / 64.f)

__device__ __align__(16) float    g_wcat[1024 * PCW];
__device__ __align__(16) float    g_proj[NROWS * PCW];
__device__ __align__(16) uint8_t  g_proj8[NROWS * PCWP];
__device__ __align__(16) uint8_t  g_w0b[20003 * 1024];
__device__ __align__(16) uint8_t  g_w1b[20000 * 256];
__device__ __align__(16) uint8_t  g_w2b[160000 * 64];
__device__ __align__(16) uint8_t  g_w3b[67735 * 64];
__device__ float g_S0[NROWS];
__device__ float g_St[NROWS];
__device__ float g_ghead[NROWS];
__device__ float g_gtail[NROWS];
__device__ int   g_rowlist[3 * NROWS];
__device__ int   g_count[3];
__device__ int   g_cluster[NROWS];

// ---------------- helpers ---------------------------------------------------
__device__ __forceinline__ uint32_t f2tf(float f) {
    uint32_t r;
    asm("cvt.rna.tf32.f32 %0, %1;" : "=r"(r) : "f"(f));
    return r;
}
__device__ __forceinline__ uint16_t pack_e4m3(float lo, float hi) {
    uint16_t r;
    asm("cvt.rn.satfinite.e4m3x2.f32 %0, %1, %2;" : "=h"(r) : "f"(hi), "f"(lo));
    return r;
}
__device__ __forceinline__ uint32_t pack4_e4m3_x8(float4 v) {
    uint16_t l = pack_e4m3(v.x * 8.f, v.y * 8.f);
    uint16_t h = pack_e4m3(v.z * 8.f, v.w * 8.f);
    return (uint32_t)l | ((uint32_t)h << 16);
}

#define MMA_TF32(c, a, b)                                                     \
    asm volatile(                                                             \
        "mma.sync.aligned.m16n8k8.row.col.f32.tf32.tf32.f32 "                 \
        "{%0,%1,%2,%3},{%4,%5,%6,%7},{%8,%9},{%0,%1,%2,%3};"                  \
        : "+f"(c[0]), "+f"(c[1]), "+f"(c[2]), "+f"(c[3])                      \
        : "r"(a[0]), "r"(a[1]), "r"(a[2]), "r"(a[3]), "r"(b[0]), "r"(b[1]))

#define MMA_FP8(c, a0, a1, a2, a3, b0, b1)                                    \
    asm volatile(                                                             \
        "mma.sync.aligned.m16n8k32.row.col.f32.e4m3.e4m3.f32 "                \
        "{%0,%1,%2,%3},{%4,%5,%6,%7},{%8,%9},{%0,%1,%2,%3};"                  \
        : "+f"(c[0]), "+f"(c[1]), "+f"(c[2]), "+f"(c[3])                      \
        : "r"(a0), "r"(a1), "r"(a2), "r"(a3), "r"(b0), "r"(b1))

#define LDSM4(r0, r1, r2, r3, addr)                                           \
    asm volatile("ldmatrix.sync.aligned.m8n8.x4.shared.b16 {%0,%1,%2,%3}, [%4];" \
        : "=r"(r0), "=r"(r1), "=r"(r2), "=r"(r3) : "r"(addr))

#define CP_ASYNC16(smem, gptr)                                                \
    asm volatile("cp.async.cg.shared.global [%0], [%1], 16;"                  \
        :: "r"(smem), "l"(gptr) : "memory")
#define CP_COMMIT()  asm volatile("cp.async.commit_group;" ::: "memory")
#define CP_WAIT(n)   asm volatile("cp.async.wait_group %0;" :: "n"(n) : "memory")

#define LDW 20                 // words per row: 16 data (64B) + 4 pad
#define MATB (128 * LDW * 4)   // 10240 B per matrix per stage
#define STAGEB (2 * MATB)      // 20480 B per stage (A then B)
#define NSTAGE 3
#define DSMEM (NSTAGE * STAGEB)

// ---------------- merged fp8 sum-exp problem table --------------------------
struct SEP {
    const uint8_t* A;
    const uint8_t* B;
    const float*   bias;
    float*         Ssum;
    int Nc, K, nx, base;
    const int* rowmap;
    const int* countPtr;
};
struct SEP4 { SEP p[4]; };

// ===========================================================================
// fp8 GEMM + fused sum-exp, 3-stage cp.async pipeline. Tile 128x128, K64
// chunks. 256 threads, 8 warps (2Mx4N). Operands x8 each -> acc = 64x logit.
// ===========================================================================
__global__ void __launch_bounds__(256, 2) fp8_sumexp_multi(SEP4 P)
{
    extern __shared__ __align__(16) uint32_t dyn[];
    __shared__ float rsum[128];

    const int bx = blockIdx.x;
    const int pi = (bx >= P.p[1].base) + (bx >= P.p[2].base) + (bx >= P.p[3].base);
    const SEP sp = P.p[pi];
    const int local = bx - sp.base;
    const int tileX = local % sp.nx;
    const int tileY = local / sp.nx;

    const int count = sp.countPtr ? *sp.countPtr : NROWS;
    const int rowBase = tileY * 128;
    if (rowBase >= count) return;
    const int colBase = tileX * 128;
    const int Nc = sp.Nc, K = sp.K;

    const int tid  = threadIdx.x;
    const int lane = tid & 31;
    const int wid  = tid >> 5;
    const int mBase = (wid & 1) * 64;
    const int nBase = (wid >> 1) * 32;
    const int lq = lane >> 2;
    const int lr = lane & 3;

    if (tid < 128) rsum[tid] = 0.f;

    // loaders: row = tid/2, half = 32 bytes of the 64B k-chunk
    const int ar   = tid >> 1;
    const int half = tid & 1;
    const int gA   = rowBase + ar;
    const bool aval = (gA < count);
    const int arow = aval ? (sp.rowmap ? sp.rowmap[gA] : gA) : 0;
    const uint8_t* Ag = sp.A + (size_t)arow * PCWP + half * 32;
    int gB = colBase + ar; if (gB >= Nc) gB = Nc - 1;
    const uint8_t* Bg = sp.B + (size_t)gB * K + half * 32;

    const uint32_t smb = (uint32_t)__cvta_generic_to_shared(dyn);
    const uint32_t aSlot = smb + (ar * LDW + half * 8) * 4;
    const uint32_t bSlot = smb + MATB + (ar * LDW + half * 8) * 4;
    const uint32_t aFrag = smb + ((mBase + (lane & 15)) * LDW + (lane >> 4) * 4) * 4;
    const uint32_t bFrag = smb + MATB + ((nBase + lane) * LDW) * 4;

    float acc[4][4][4];
#pragma unroll
    for (int i = 0; i < 4; i++)
#pragma unroll
        for (int j = 0; j < 4; j++)
#pragma unroll
            for (int r = 0; r < 4; r++) acc[i][j][r] = 0.f;

    const int nch = K >> 6;

    // prologue: stage chunks 0 (and 1) into buffers 0 (and 1)
    CP_ASYNC16(aSlot, Ag);          CP_ASYNC16(aSlot + 16, Ag + 16);
    CP_ASYNC16(bSlot, Bg);          CP_ASYNC16(bSlot + 16, Bg + 16);
    CP_COMMIT();
    if (nch > 1) {
        CP_ASYNC16(aSlot + STAGEB, Ag + 64);      CP_ASYNC16(aSlot + STAGEB + 16, Ag + 80);
        CP_ASYNC16(bSlot + STAGEB, Bg + 64);      CP_ASYNC16(bSlot + STAGEB + 16, Bg + 80);
        CP_COMMIT();
    }

    int buf = 0;
    for (int c = 0; c < nch; ++c) {
        if (c + 1 < nch) CP_WAIT(1); else CP_WAIT(0);
        __syncthreads();

        if (c + 2 < nch) {
            int nb = buf + 2; if (nb >= NSTAGE) nb -= NSTAGE;
            const uint32_t off = nb * STAGEB;
            const uint8_t* an = Ag + ((c + 2) << 6);
            const uint8_t* bn = Bg + ((c + 2) << 6);
            CP_ASYNC16(aSlot + off, an); CP_ASYNC16(aSlot + off + 16, an + 16);
            CP_ASYNC16(bSlot + off, bn); CP_ASYNC16(bSlot + off + 16, bn + 16);
            CP_COMMIT();
        }

        const uint32_t aB = aFrag + buf * STAGEB;
        const uint32_t bB = bFrag + buf * STAGEB;
#pragma unroll
        for (int cc = 0; cc < 2; ++cc) {
            uint32_t af[4][4], b0r[4], b1r[4];
            LDSM4(b0r[0], b0r[1], b0r[2], b0r[3], bB + cc * 32);
            LDSM4(b1r[0], b1r[1], b1r[2], b1r[3], bB + cc * 32 + 16);
#pragma unroll
            for (int mt = 0; mt < 4; mt++)
                LDSM4(af[mt][0], af[mt][1], af[mt][2], af[mt][3],
                      aB + mt * (16 * LDW * 4) + cc * 32);
#pragma unroll
            for (int mt = 0; mt < 4; mt++)
#pragma unroll
                for (int nt = 0; nt < 4; nt++)
                    MMA_FP8(acc[mt][nt],
                            af[mt][0], af[mt][1], af[mt][2], af[mt][3],
                            b0r[nt], b1r[nt]);
        }

        if (++buf == NSTAGE) buf = 0;
    }

    // fused sum-exp epilogue (exp2, folded scales)
    float rs[4][2];
#pragma unroll
    for (int mt = 0; mt < 4; mt++) { rs[mt][0] = 0.f; rs[mt][1] = 0.f; }

    const float* bptr = sp.bias + colBase + nBase;
    if (colBase + 128 <= Nc) {
#pragma unroll
        for (int nt = 0; nt < 4; nt++) {
            int cc0 = nt * 8 + 2 * lr;
            float bv0 = bptr[cc0] * LOG2E;
            float bv1 = bptr[cc0 + 1] * LOG2E;
#pragma unroll
            for (int mt = 0; mt < 4; mt++) {
                rs[mt][0] += exp2f(fmaf(acc[mt][nt][0], INV64_LOG2E, bv0));
                rs[mt][1] += exp2f(fmaf(acc[mt][nt][2], INV64_LOG2E, bv0));
                rs[mt][0] += exp2f(fmaf(acc[mt][nt][1], INV64_LOG2E, bv1));
                rs[mt][1] += exp2f(fmaf(acc[mt][nt][3], INV64_LOG2E, bv1));
            }
        }
    } else {
#pragma unroll
        for (int nt = 0; nt < 4; nt++) {
            int gc = colBase + nBase + nt * 8 + 2 * lr;
            bool v0 = gc < Nc, v1 = (gc + 1) < Nc;
            float bv0 = v0 ? sp.bias[gc] * LOG2E : 0.f;
            float bv1 = v1 ? sp.bias[gc + 1] * LOG2E : 0.f;
#pragma unroll
            for (int mt = 0; mt < 4; mt++) {
                if (v0) {
                    rs[mt][0] += exp2f(fmaf(acc[mt][nt][0], INV64_LOG2E, bv0));
                    rs[mt][1] += exp2f(fmaf(acc[mt][nt][2], INV64_LOG2E, bv0));
                }
                if (v1) {
                    rs[mt][0] += exp2f(fmaf(acc[mt][nt][1], INV64_LOG2E, bv1));
                    rs[mt][1] += exp2f(fmaf(acc[mt][nt][3], INV64_LOG2E, bv1));
                }
            }
        }
    }
#pragma unroll
    for (int mt = 0; mt < 4; mt++)
#pragma unroll
        for (int h = 0; h < 2; h++) {
            float v = rs[mt][h];
            v += __shfl_xor_sync(0xffffffffu, v, 1);
            v += __shfl_xor_sync(0xffffffffu, v, 2);
            if (lr == 0)
                atomicAdd(&rsum[mBase + mt * 16 + h * 8 + lq], v);
        }
    __syncthreads();
    if (tid < 128) {
        int gr = rowBase + tid;
        if (gr < count) {
            int n = sp.rowmap ? sp.rowmap[gr] : gr;
            atomicAdd(&sp.Ssum[n], rsum[tid]);
        }
    }
}

// ===========================================================================
// tf32 mma.sync GEMM (proj store path). C fp32 [M,Nc] + fp8 x8 copy at
// row stride PCWP. B [K,Nc] row-major (NN).
// ===========================================================================
__global__ void __launch_bounds__(256, 2) proj_gemm(
    const float* __restrict__ A, const float* __restrict__ B,
    float* __restrict__ C, uint8_t* __restrict__ C8, int Nc, int K)
{
    __shared__ uint32_t As[128 * LDW];
    __shared__ uint32_t Bs[128 * LDW];

    const int rowBase = blockIdx.y * 128;
    const int colBase = blockIdx.x * 128;

    const int tid  = threadIdx.x;
    const int lane = tid & 31;
    const int wid  = tid >> 5;
    const int mBase = (wid & 1) * 64;
    const int nBase = (wid >> 1) * 32;
    const int lq = lane >> 2;
    const int lr = lane & 3;

    const int ar  = tid >> 1;
    const int akk = (tid & 1) * 8;
    const float* Aptr = A + (size_t)(rowBase + ar) * K + akk;

    const int bkk = tid >> 4;
    const int br  = (tid & 15) * 8;
    const bool bval = (colBase + br) < Nc;
    const float* Bptr = B + colBase + (bval ? br : 0);

    const float4 fz = make_float4(0.f, 0.f, 0.f, 0.f);
    float4 aR0, aR1, bR0, bR1;
    aR0 = *(const float4*)(Aptr);
    aR1 = *(const float4*)(Aptr + 4);
    bR0 = bval ? *(const float4*)(Bptr + (size_t)bkk * Nc)     : fz;
    bR1 = bval ? *(const float4*)(Bptr + (size_t)bkk * Nc + 4) : fz;

    float acc[4][4][4];
#pragma unroll
    for (int i = 0; i < 4; i++)
#pragma unroll
        for (int j = 0; j < 4; j++)
#pragma unroll
            for (int r = 0; r < 4; r++) acc[i][j][r] = 0.f;

    for (int k0 = 0; k0 < K; k0 += 16) {
        {
            uint32_t* ap = &As[ar * LDW + akk];
            ap[0] = f2tf(aR0.x); ap[1] = f2tf(aR0.y); ap[2] = f2tf(aR0.z); ap[3] = f2tf(aR0.w);
            ap[4] = f2tf(aR1.x); ap[5] = f2tf(aR1.y); ap[6] = f2tf(aR1.z); ap[7] = f2tf(aR1.w);
            float v[8] = {bR0.x, bR0.y, bR0.z, bR0.w, bR1.x, bR1.y, bR1.z, bR1.w};
#pragma unroll
            for (int q = 0; q < 8; q++) Bs[(br + q) * LDW + bkk] = f2tf(v[q]);
        }
        __syncthreads();

        const int kn = k0 + 16;
        if (kn < K) {
            aR0 = *(const float4*)(Aptr + kn);
            aR1 = *(const float4*)(Aptr + kn + 4);
            bR0 = bval ? *(const float4*)(Bptr + (size_t)(kn + bkk) * Nc)     : fz;
            bR1 = bval ? *(const float4*)(Bptr + (size_t)(kn + bkk) * Nc + 4) : fz;
        }

#pragma unroll
        for (int ks = 0; ks < 16; ks += 8) {
            uint32_t af[4][4], bf[4][2];
#pragma unroll
            for (int mt = 0; mt < 4; mt++) {
                int r = mBase + mt * 16 + lq;
                int c = ks + lr;
                af[mt][0] = As[r * LDW + c];
                af[mt][1] = As[(r + 8) * LDW + c];
                af[mt][2] = As[r * LDW + c + 4];
                af[mt][3] = As[(r + 8) * LDW + c + 4];
            }
#pragma unroll
            for (int nt = 0; nt < 4; nt++) {
                int n = nBase + nt * 8 + lq;
                bf[nt][0] = Bs[n * LDW + ks + lr];
                bf[nt][1] = Bs[n * LDW + ks + 4 + lr];
            }
#pragma unroll
            for (int mt = 0; mt < 4; mt++)
#pragma unroll
                for (int nt = 0; nt < 4; nt++)
                    MMA_TF32(acc[mt][nt], af[mt], bf[nt]);
        }
        __syncthreads();
    }

#pragma unroll
    for (int mt = 0; mt < 4; mt++) {
        int r0 = rowBase + mBase + mt * 16 + lq;
#pragma unroll
        for (int nt = 0; nt < 4; nt++) {
            int gc = colBase + nBase + nt * 8 + 2 * lr;
            if (gc < Nc) {
                float* p0 = C + (size_t)r0 * Nc + gc;
                float* p1 = C + (size_t)(r0 + 8) * Nc + gc;
                p0[0] = acc[mt][nt][0]; p0[1] = acc[mt][nt][1];
                p1[0] = acc[mt][nt][2]; p1[1] = acc[mt][nt][3];
                ((uint16_t*)C8)[((size_t)r0 * PCWP + gc) >> 1] =
                    pack_e4m3(acc[mt][nt][0] * 8.f, acc[mt][nt][1] * 8.f);
                ((uint16_t*)C8)[((size_t)(r0 + 8) * PCWP + gc) >> 1] =
                    pack_e4m3(acc[mt][nt][2] * 8.f, acc[mt][nt][3] * 8.f);
            }
        }
    }
}

// ---------------- prep / bufprep / gather / combine -------------------------
__global__ void prep_kernel(const int* __restrict__ target) {
    int i = threadIdx.x;
    g_S0[i] = 0.f; g_St[i] = 0.f;
    if (i < 3) g_count[i] = 0;
    __syncthreads();
    int t = target[i];
    int c = (t < 20000) ? 0 : (t < 40000) ? 1 : (t < 200000) ? 2 : 3;
    g_cluster[i] = c;
    if (c > 0) {
        int idx = atomicAdd(&g_count[c - 1], 1);
        g_rowlist[(c - 1) * NROWS + idx] = i;
    }
}

__global__ void bufprep_kernel(
    const float4* __restrict__ p0, const float4* __restrict__ p1,
    const float4* __restrict__ p2, const float4* __restrict__ p3,
    const float4* __restrict__ w0, const float4* __restrict__ w1,
    const float4* __restrict__ w2, const float4* __restrict__ w3)
{
    const int T0 = 348160;            // wcat: 1024*1360/4
    const int T1 = T0 + 5120768;      // w0:   20003*1024/4
    const int T2 = T1 + 1280000;      // w1:   20000*256/4
    const int T3 = T2 + 2560000;      // w2:   160000*64/4
    const int T4 = T3 + 270940;       // w3:   67735*16/4 (data)
    const int T5 = T4 + 812820;       // w3 pad zeros: 67735*12
    const int T6 = T5 + 12288;        // proj8 pad zeros: 1024*12
    for (int i = blockIdx.x * blockDim.x + threadIdx.x; i < T6;
         i += gridDim.x * blockDim.x) {
        if (i < T0) {
            int k = i / 340, c4 = i - k * 340;
            float4 v;
            if (c4 < 256)      v = p0[k * 256 + c4];
            else if (c4 < 320) v = p1[k * 64 + (c4 - 256)];
            else if (c4 < 336) v = p2[k * 16 + (c4 - 320)];
            else               v = p3[k * 4 + (c4 - 336)];
            ((float4*)g_wcat)[i] = v;
        } else if (i < T1) {
            int j = i - T0;
            ((uint32_t*)g_w0b)[j] = pack4_e4m3_x8(w0[j]);
        } else if (i < T2) {
            int j = i - T1;
            ((uint32_t*)g_w1b)[j] = pack4_e4m3_x8(w1[j]);
        } else if (i < T3) {
            int j = i - T2;
            ((uint32_t*)g_w2b)[j] = pack4_e4m3_x8(w2[j]);
        } else if (i < T4) {
            int j = i - T3;
            int row = j >> 2, q = j & 3;
            ((uint32_t*)g_w3b)[row * 16 + q] = pack4_e4m3_x8(w3[j]);
        } else if (i < T5) {
            int j = i - T4;
            int row = j / 12, word = j - row * 12;
            ((uint32_t*)g_w3b)[row * 16 + 4 + word] = 0u;
        } else {
            int j = i - T5;
            int row = j / 12, word = j - row * 12;
            ((uint32_t*)g_proj8)[row * 352 + 340 + word] = 0u;
        }
    }
}

__global__ void gather_kernel(
    const float* __restrict__ w0, const float* __restrict__ b0,
    const float* __restrict__ w1, const float* __restrict__ b1,
    const float* __restrict__ w2, const float* __restrict__ b2,
    const float* __restrict__ w3, const float* __restrict__ b3,
    const int* __restrict__ target)
{
    int gw = (blockIdx.x * blockDim.x + threadIdx.x) >> 5;
    int lane = threadIdx.x & 31;
    if (gw < NROWS) {
        int c = g_cluster[gw];
        int col = (c == 0) ? target[gw] : (HEAD_SIZE - c);
        const float4* pr = (const float4*)(g_proj + (size_t)gw * PCW);
        const float4* wr = (const float4*)(w0 + (size_t)col * 1024);
        float s = 0.f;
        for (int i = lane; i < 256; i += 32) {
            float4 a = pr[i], b = wr[i];
            s += a.x * b.x + a.y * b.y + a.z * b.z + a.w * b.w;
        }
#pragma unroll
        for (int o = 16; o; o >>= 1) s += __shfl_down_sync(0xffffffffu, s, o);
        if (lane == 0) g_ghead[gw] = s + b0[col];
    } else if (gw < 2 * NROWS) {
        int w = gw - NROWS;
        int c = g_cluster[w];
        if (c == 0) return;
        const float* pr; const float* W; const float* bb; int K, off;
        if (c == 1)      { pr = g_proj + (size_t)w * PCW + 1024; W = w1; bb = b1; K = 256; off = 20000; }
        else if (c == 2) { pr = g_proj + (size_t)w * PCW + 1280; W = w2; bb = b2; K = 64;  off = 40000; }
        else             { pr = g_proj + (size_t)w * PCW + 1344; W = w3; bb = b3; K = 16;  off = 200000; }
        int ti = target[w] - off;
        float s = 0.f;
        for (int k = lane; k < K; k += 32) s += pr[k] * W[(size_t)ti * K + k];
#pragma unroll
        for (int o = 16; o; o >>= 1) s += __shfl_down_sync(0xffffffffu, s, o);
        if (lane == 0) g_gtail[w] = s + bb[ti];
    }
}

__global__ void combine_kernel(float* __restrict__ out, int n) {
    int i = blockIdx.x * blockDim.x + threadIdx.x;
    if (i >= n) return;
    float v = logf(g_S0[i]) - g_ghead[i];
    if (g_cluster[i] > 0) v += logf(g_St[i]) - g_gtail[i];
    out[i] = v;
}

// ---------------- launch ----------------------------------------------------
extern "C" void kernel_launch(void* const* d_in, const int* in_sizes, int n_in,
                              void* d_out, int out_size) {
    const float* hidden = (const float*)d_in[0];
    const int*   target = (const int*)d_in[1];
    const float* w0 = (const float*)d_in[2];
    const float* b0 = (const float*)d_in[3];
    const float* p0 = (const float*)d_in[4];
    const float* w1 = (const float*)d_in[5];
    const float* b1 = (const float*)d_in[6];
    const float* p1 = (const float*)d_in[7];
    const float* w2 = (const float*)d_in[8];
    const float* b2 = (const float*)d_in[9];
    const float* p2 = (const float*)d_in[10];
    const float* w3 = (const float*)d_in[11];
    const float* b3 = (const float*)d_in[12];
    const float* p3 = (const float*)d_in[13];
    float* out = (float*)d_out;

    float *wcat, *proj, *S0, *St;
    uint8_t *proj8, *w0b, *w1b, *w2b, *w3b;
    int *rowlist, *cnt;
    cudaGetSymbolAddress((void**)&wcat, g_wcat);
    cudaGetSymbolAddress((void**)&proj, g_proj);
    cudaGetSymbolAddress((void**)&proj8, g_proj8);
    cudaGetSymbolAddress((void**)&w0b, g_w0b);
    cudaGetSymbolAddress((void**)&w1b, g_w1b);
    cudaGetSymbolAddress((void**)&w2b, g_w2b);
    cudaGetSymbolAddress((void**)&w3b, g_w3b);
    cudaGetSymbolAddress((void**)&S0, g_S0);
    cudaGetSymbolAddress((void**)&St, g_St);
    cudaGetSymbolAddress((void**)&rowlist, g_rowlist);
    cudaGetSymbolAddress((void**)&cnt, g_count);

    const int N = NROWS;

    static bool attrDone = false;
    if (!attrDone) {
        cudaFuncSetAttribute(fp8_sumexp_multi,
                             cudaFuncAttributeMaxDynamicSharedMemorySize, DSMEM);
        attrDone = true;
    }

    prep_kernel<<<1, 1024>>>(target);
    bufprep_kernel<<<2048, 256>>>((const float4*)p0, (const float4*)p1,
                                  (const float4*)p2, (const float4*)p3,
                                  (const float4*)w0, (const float4*)w1,
                                  (const float4*)w2, (const float4*)w3);

    // proj_cat = hidden @ wcat  (tf32 NN, fp32 + fp8 outputs)
    proj_gemm<<<dim3(11, 8, 1), 256>>>(hidden, wcat, proj, proj8, PCW, 1024);

    // ONE merged fp8 sum-exp launch: head, tail1, tail3, tail2
    SEP4 P;
    P.p[0] = { proj8,        w0b, b0, S0, HEAD_SIZE, 1024, 157, 0,
               nullptr, nullptr };                                   // 1256
    P.p[1] = { proj8 + 1024, w1b, b1, St, 20000, 256, 157, 1256,
               rowlist + 0 * NROWS, cnt + 0 };                       // 1256
    P.p[2] = { proj8 + 1344, w3b, b3, St, 67735, 64, 530, 2512,
               rowlist + 2 * NROWS, cnt + 2 };                       // 4240
    P.p[3] = { proj8 + 1280, w2b, b2, St, 160000, 64, 1250, 6752,
               rowlist + 1 * NROWS, cnt + 1 };                       // 10000
    fp8_sumexp_multi<<<16752, 256, DSMEM>>>(P);

    gather_kernel<<<256, 256>>>(w0, b0, w1, b1, w2, b2, w3, b3, target);
    combine_kernel<<<(N + 255) / 256, 256>>>(out, N);
}